// round 6
// baseline (speedup 1.0000x reference)
#include <cuda_runtime.h>
#include <math.h>
#include <stdint.h>

#define S_LEN 2048
#define BATCH 2
#define HID 2048
#define NHEAD 16
#define HDIM 128
#define QKV_N 6144
#define ROWS 4096

// ---------------- scratch (device globals; allocation forbidden) -----------
__device__ uint32_t g_hs_t[(size_t)ROWS * HID];      // tf32 bits of hidden_states
__device__ uint32_t g_wqkv_t[(size_t)QKV_N * HID];   // tf32 bits of w_qkv
__device__ uint32_t g_wd_t[(size_t)HID * HID];       // tf32 bits of w_dense
__device__ uint32_t g_qkv[(size_t)ROWS * QKV_N];     // tf32 bits of qkv
__device__ uint32_t g_ctx_t[(size_t)ROWS * HID];     // tf32 bits of ctx

// ---------------- helpers --------------------------------------------------
__device__ __forceinline__ uint32_t f2tf(float x) {
    uint32_t r; asm("cvt.rna.tf32.f32 %0, %1;" : "=r"(r) : "f"(x)); return r;
}
__device__ __forceinline__ void mma8(float* c, const uint32_t* a, uint32_t b0, uint32_t b1) {
    asm volatile("mma.sync.aligned.m16n8k8.row.col.f32.tf32.tf32.f32 "
        "{%0,%1,%2,%3},{%4,%5,%6,%7},{%8,%9},{%0,%1,%2,%3};"
        : "+f"(c[0]), "+f"(c[1]), "+f"(c[2]), "+f"(c[3])
        : "r"(a[0]), "r"(a[1]), "r"(a[2]), "r"(a[3]), "r"(b0), "r"(b1));
}
__device__ __forceinline__ void cp16(uint32_t saddr, const void* gptr) {
    asm volatile("cp.async.cg.shared.global [%0], [%1], 16;" :: "r"(saddr), "l"(gptr));
}
__device__ __forceinline__ uint32_t smem_u32(const void* p) {
    uint32_t a;
    asm("{ .reg .u64 t; cvta.to.shared.u64 t, %1; cvt.u32.u64 %0, t; }" : "=r"(a) : "l"(p));
    return a;
}

// ---------------- fp32 -> tf32 conversion kernel ---------------------------
__global__ void cvt_tf32_kernel(const float4* __restrict__ in, uint4* __restrict__ out, int n4) {
    int i = blockIdx.x * blockDim.x + threadIdx.x;
    if (i < n4) {
        float4 v = in[i];
        uint4 o;
        o.x = f2tf(v.x); o.y = f2tf(v.y); o.z = f2tf(v.z); o.w = f2tf(v.w);
        out[i] = o;
    }
}

// ---------------- tf32 GEMM: C[m,n] = A[m,:] . B[n,:] (+bias) --------------
// A: [M,K] tf32 bits row-major. B: [N,K] tf32 bits row-major.
// Block 128x128, BK=32, 3-stage cp.async, 8 warps (2x4) with 64x32 warp tiles.
// Fragment ping-pong prefetch across the 4 kk-steps; one __syncthreads/iter.
// out_tf32: write C as tf32 bits (for qkv); else raw fp32 bits.
#define GBM 128
#define GBN 128
#define GBK 32
#define SLD 36
#define TSZ (128 * SLD)
#define GEMM_SMEM_BYTES (3 * 2 * TSZ * 4)       // 110592

__global__ __launch_bounds__(256, 2)
void gemm_tf32(const uint32_t* __restrict__ A, const uint32_t* __restrict__ B,
               const float* __restrict__ bias, uint32_t* __restrict__ C,
               int M, int N, int K, int add_bias, int out_tf32)
{
    extern __shared__ uint32_t sm[];

    const int tid = threadIdx.x;
    const int lane = tid & 31, warp = tid >> 5;
    const int g = lane >> 2, tg = lane & 3;
    const int wm = warp >> 2, wn = warp & 3;     // 2 x 4 warps
    const int m0 = blockIdx.y * GBM, n0 = blockIdx.x * GBN;

    float c[4][4][4];
#pragma unroll
    for (int i = 0; i < 4; i++)
#pragma unroll
        for (int j = 0; j < 4; j++)
#pragma unroll
            for (int q = 0; q < 4; q++) c[i][j][q] = 0.f;

    auto load_stage = [&](int it, int buf) {
        uint32_t* Ab = sm + buf * 2 * TSZ;
        uint32_t* Bb = Ab + TSZ;
        uint32_t ab = (uint32_t)__cvta_generic_to_shared(Ab);
        uint32_t bb = (uint32_t)__cvta_generic_to_shared(Bb);
        const int k0 = it * GBK;
#pragma unroll
        for (int t = 0; t < 4; t++) {            // 128 rows x 8 16B-chunks
            int fid = tid + 256 * t;
            int r = fid >> 3, c4 = (fid & 7) * 4;
            cp16(ab + (uint32_t)(r * SLD + c4) * 4, A + (size_t)(m0 + r) * K + k0 + c4);
            cp16(bb + (uint32_t)(r * SLD + c4) * 4, B + (size_t)(n0 + r) * K + k0 + c4);
        }
        asm volatile("cp.async.commit_group;" ::: "memory");
    };

    const int NI = K / GBK;
    load_stage(0, 0);
    load_stage(1, 1);

    for (int it = 0; it < NI; it++) {
        asm volatile("cp.async.wait_group 1;" ::: "memory");
        __syncthreads();                         // visibility + all warps done prior reads
        if (it + 2 < NI) load_stage(it + 2, (it + 2) % 3);

        const uint32_t* Ab = sm + (it % 3) * 2 * TSZ;
        const uint32_t* Bb = Ab + TSZ;

        uint32_t aF[2][4][4], bF[2][4][2];
#pragma unroll
        for (int i = 0; i < 4; i++) {
            const uint32_t* p = Ab + (wm * 64 + i * 16 + g) * SLD + tg;
            aF[0][i][0] = p[0]; aF[0][i][1] = p[8 * SLD];
            aF[0][i][2] = p[4]; aF[0][i][3] = p[8 * SLD + 4];
        }
#pragma unroll
        for (int j = 0; j < 4; j++) {
            const uint32_t* p = Bb + (wn * 32 + j * 8 + g) * SLD + tg;
            bF[0][j][0] = p[0]; bF[0][j][1] = p[4];
        }
#pragma unroll
        for (int kk = 0; kk < 4; kk++) {
            const int cur = kk & 1, nxt = cur ^ 1;
            if (kk < 3) {
#pragma unroll
                for (int i = 0; i < 4; i++) {
                    const uint32_t* p = Ab + (wm * 64 + i * 16 + g) * SLD + (kk + 1) * 8 + tg;
                    aF[nxt][i][0] = p[0]; aF[nxt][i][1] = p[8 * SLD];
                    aF[nxt][i][2] = p[4]; aF[nxt][i][3] = p[8 * SLD + 4];
                }
#pragma unroll
                for (int j = 0; j < 4; j++) {
                    const uint32_t* p = Bb + (wn * 32 + j * 8 + g) * SLD + (kk + 1) * 8 + tg;
                    bF[nxt][j][0] = p[0]; bF[nxt][j][1] = p[4];
                }
            }
#pragma unroll
            for (int j = 0; j < 4; j++)
#pragma unroll
                for (int i = 0; i < 4; i++)
                    mma8(c[i][j], aF[cur][i], bF[cur][j][0], bF[cur][j][1]);
        }
    }

#pragma unroll
    for (int i = 0; i < 4; i++) {
        int row = m0 + wm * 64 + i * 16 + g;
#pragma unroll
        for (int j = 0; j < 4; j++) {
            int col = n0 + wn * 32 + j * 8 + 2 * tg;
            float b0 = add_bias ? bias[col] : 0.f;
            float b1 = add_bias ? bias[col + 1] : 0.f;
            float v00 = c[i][j][0] + b0, v01 = c[i][j][1] + b1;
            float v10 = c[i][j][2] + b0, v11 = c[i][j][3] + b1;
            uint2 r0, r1;
            if (out_tf32) {
                r0.x = f2tf(v00); r0.y = f2tf(v01);
                r1.x = f2tf(v10); r1.y = f2tf(v11);
            } else {
                r0.x = __float_as_uint(v00); r0.y = __float_as_uint(v01);
                r1.x = __float_as_uint(v10); r1.y = __float_as_uint(v11);
            }
            *(uint2*)(C + (size_t)row * N + col) = r0;
            *(uint2*)(C + (size_t)(row + 8) * N + col) = r1;
        }
    }
}

// ---------------- tf32 flash attention (qkv already tf32 bits) --------------
// Q tile 128 rows (warp owns 16), K/V chunks of 32 rows, double-buffered
// cp.async so the kt+1 load overlaps kt's compute. 8 warps, 1 CTA/SM.
#define AQ_LD 132
#define AK_LD 132
#define AV_LD 136
#define AP_LD 36
#define KCH 32
#define KVBUF (KCH * AK_LD + KCH * AV_LD)
#define ATT_WORDS (128 * AQ_LD + 2 * KVBUF + 128 * AP_LD)
#define ATT_BYTES (ATT_WORDS * 4)               // 154624

__global__ __launch_bounds__(256, 1)
void attn_tf32(const uint32_t* __restrict__ qkv, uint32_t* __restrict__ ctx)
{
    extern __shared__ uint32_t sm[];
    uint32_t* Qs = sm;
    uint32_t* KV = Qs + 128 * AQ_LD;
    uint32_t* Ps = KV + 2 * KVBUF;
    const uint32_t kvb = smem_u32(KV);

    const int tid = threadIdx.x, lane = tid & 31, warp = tid >> 5;
    const int g = lane >> 2, tg = lane & 3;
    const int qt = gridDim.x - 1 - blockIdx.x;   // heavy tiles first
    const int head = blockIdx.y, bb = blockIdx.z;
    const int q0 = qt * 128;
    const size_t hoff = (size_t)head * (3 * HDIM);

    auto load_kv = [&](int kt) {
        const int b = kt & 1;
        const uint32_t kb = kvb + (uint32_t)(b * KVBUF) * 4;
        const uint32_t vb = kb + (uint32_t)(KCH * AK_LD) * 4;
        const int kr0 = kt * KCH;
#pragma unroll
        for (int t = 0; t < 4; t++) {            // 1024 chunks of 16B per tile
            int fid = tid + 256 * t;
            int r = fid >> 5, c4 = (fid & 31) * 4;
            const uint32_t* s = qkv + ((size_t)(kr0 + r) * BATCH + bb) * QKV_N + hoff + HDIM + c4;
            cp16(kb + (uint32_t)(r * AK_LD + c4) * 4, s);
            cp16(vb + (uint32_t)(r * AV_LD + c4) * 4, s + HDIM);
        }
        asm volatile("cp.async.commit_group;" ::: "memory");
    };

    // Q tile via cp.async (raw tf32 bits)
    {
        uint32_t qsb = smem_u32(Qs);
#pragma unroll
        for (int t = 0; t < 16; t++) {
            int fid = tid + 256 * t;
            int r = fid >> 5, c4 = (fid & 31) * 4;
            const uint32_t* s = qkv + ((size_t)(q0 + r) * BATCH + bb) * QKV_N + hoff + c4;
            cp16(qsb + (uint32_t)(r * AQ_LD + c4) * 4, s);
        }
    }
    load_kv(0);   // commits Q + KV chunk 0 as one group

    float o[16][4];
#pragma unroll
    for (int j = 0; j < 16; j++)
#pragma unroll
        for (int q = 0; q < 4; q++) o[j][q] = 0.f;
    float m0r = -1e30f, m1r = -1e30f, l0r = 0.f, l1r = 0.f;
    const float scale = 0.08838834764831845f;    // 1/sqrt(128)

    const int nkt = 4 * qt + 4;
    for (int kt = 0; kt < nkt; kt++) {
        asm volatile("cp.async.wait_group 0;" ::: "memory");
        __syncthreads();                         // data visible + prior readers done
        if (kt + 1 < nkt) load_kv(kt + 1);       // overlaps this iter's compute

        const int b = kt & 1;
        const uint32_t* Kb = KV + b * KVBUF;
        const uint32_t* Vb = Kb + KCH * AK_LD;
        const int kr0 = kt * KCH;
        const int rowg = q0 + warp * 16 + g;
        const bool active = (kr0 <= q0 + warp * 16 + 15);

        if (active) {
            // S = Q @ K^T  (warp: 16 rows x 32 cols)
            float s[4][4];
#pragma unroll
            for (int j = 0; j < 4; j++)
#pragma unroll
                for (int q = 0; q < 4; q++) s[j][q] = 0.f;
#pragma unroll
            for (int kk = 0; kk < 16; kk++) {
                uint32_t a[4];
                const uint32_t* qp = Qs + (warp * 16 + g) * AQ_LD + kk * 8 + tg;
                a[0] = qp[0]; a[1] = qp[8 * AQ_LD]; a[2] = qp[4]; a[3] = qp[8 * AQ_LD + 4];
#pragma unroll
                for (int j = 0; j < 4; j++) {
                    const uint32_t* kp = Kb + (j * 8 + g) * AK_LD + kk * 8 + tg;
                    mma8(s[j], a, kp[0], kp[4]);
                }
            }
#pragma unroll
            for (int j = 0; j < 4; j++) {
                int cb = kr0 + j * 8 + 2 * tg;
                s[j][0] = (cb     > rowg)     ? -10000.f : s[j][0] * scale;
                s[j][1] = (cb + 1 > rowg)     ? -10000.f : s[j][1] * scale;
                s[j][2] = (cb     > rowg + 8) ? -10000.f : s[j][2] * scale;
                s[j][3] = (cb + 1 > rowg + 8) ? -10000.f : s[j][3] * scale;
            }
            {
                float ml = -1e30f;
#pragma unroll
                for (int j = 0; j < 4; j++) ml = fmaxf(ml, fmaxf(s[j][0], s[j][1]));
                ml = fmaxf(ml, __shfl_xor_sync(0xffffffffu, ml, 1));
                ml = fmaxf(ml, __shfl_xor_sync(0xffffffffu, ml, 2));
                float mn = fmaxf(m0r, ml);
                float corr = __expf(m0r - mn);
                float ps = 0.f;
#pragma unroll
                for (int j = 0; j < 4; j++) {
                    s[j][0] = __expf(s[j][0] - mn);
                    s[j][1] = __expf(s[j][1] - mn);
                    ps += s[j][0] + s[j][1];
                }
                ps += __shfl_xor_sync(0xffffffffu, ps, 1);
                ps += __shfl_xor_sync(0xffffffffu, ps, 2);
                l0r = l0r * corr + ps; m0r = mn;
#pragma unroll
                for (int j = 0; j < 16; j++) { o[j][0] *= corr; o[j][1] *= corr; }
            }
            {
                float ml = -1e30f;
#pragma unroll
                for (int j = 0; j < 4; j++) ml = fmaxf(ml, fmaxf(s[j][2], s[j][3]));
                ml = fmaxf(ml, __shfl_xor_sync(0xffffffffu, ml, 1));
                ml = fmaxf(ml, __shfl_xor_sync(0xffffffffu, ml, 2));
                float mn = fmaxf(m1r, ml);
                float corr = __expf(m1r - mn);
                float ps = 0.f;
#pragma unroll
                for (int j = 0; j < 4; j++) {
                    s[j][2] = __expf(s[j][2] - mn);
                    s[j][3] = __expf(s[j][3] - mn);
                    ps += s[j][2] + s[j][3];
                }
                ps += __shfl_xor_sync(0xffffffffu, ps, 1);
                ps += __shfl_xor_sync(0xffffffffu, ps, 2);
                l1r = l1r * corr + ps; m1r = mn;
#pragma unroll
                for (int j = 0; j < 16; j++) { o[j][2] *= corr; o[j][3] *= corr; }
            }
            // P -> smem (tf32) for re-fragmenting (own rows only)
#pragma unroll
            for (int j = 0; j < 4; j++) {
                uint32_t* p0 = Ps + (warp * 16 + g) * AP_LD + j * 8 + 2 * tg;
                p0[0] = f2tf(s[j][0]); p0[1] = f2tf(s[j][1]);
                uint32_t* p1 = p0 + 8 * AP_LD;
                p1[0] = f2tf(s[j][2]); p1[1] = f2tf(s[j][3]);
            }
        }
        __syncwarp();
        if (active) {
            // O += P @ V  (16 rows x 128 cols, k=32)
#pragma unroll
            for (int kk = 0; kk < 4; kk++) {
                uint32_t a[4];
                const uint32_t* pp = Ps + (warp * 16 + g) * AP_LD + kk * 8 + tg;
                a[0] = pp[0]; a[1] = pp[8 * AP_LD]; a[2] = pp[4]; a[3] = pp[8 * AP_LD + 4];
#pragma unroll
                for (int j = 0; j < 16; j++) {
                    const uint32_t* vp = Vb + (kk * 8 + tg) * AV_LD + j * 8 + g;
                    mma8(o[j], a, vp[0], vp[4 * AV_LD]);
                }
            }
        }
    }

    const float i0 = 1.f / l0r, i1 = 1.f / l1r;
    const int r0g = q0 + warp * 16 + g;
#pragma unroll
    for (int j = 0; j < 16; j++) {
        int col = head * HDIM + j * 8 + 2 * tg;
        uint2 v0 = { f2tf(o[j][0] * i0), f2tf(o[j][1] * i0) };
        uint2 v1 = { f2tf(o[j][2] * i1), f2tf(o[j][3] * i1) };
        *(uint2*)(ctx + ((size_t)r0g * BATCH + bb) * HID + col) = v0;
        *(uint2*)(ctx + ((size_t)(r0g + 8) * BATCH + bb) * HID + col) = v1;
    }
}

// ---------------------------------------------------------------------------
extern "C" void kernel_launch(void* const* d_in, const int* in_sizes, int n_in,
                              void* d_out, int out_size)
{
    const float* hs      = (const float*)d_in[0];
    const float* w_qkv   = (const float*)d_in[2];
    const float* b_qkv   = (const float*)d_in[3];
    const float* w_dense = (const float*)d_in[4];
    const float* b_dense = (const float*)d_in[5];
    float* out = (float*)d_out;

    uint32_t *hs_t, *wqkv_t, *wd_t, *ctx_t, *qkv_buf;
    cudaGetSymbolAddress((void**)&hs_t, g_hs_t);
    cudaGetSymbolAddress((void**)&wqkv_t, g_wqkv_t);
    cudaGetSymbolAddress((void**)&wd_t, g_wd_t);
    cudaGetSymbolAddress((void**)&qkv_buf, g_qkv);
    cudaGetSymbolAddress((void**)&ctx_t, g_ctx_t);

    cudaFuncSetAttribute(gemm_tf32, cudaFuncAttributeMaxDynamicSharedMemorySize, GEMM_SMEM_BYTES);
    cudaFuncSetAttribute(attn_tf32, cudaFuncAttributeMaxDynamicSharedMemorySize, ATT_BYTES);

    // 0) pre-round GEMM operands to tf32 (rna)
    {
        int n4;
        n4 = ROWS * HID / 4;
        cvt_tf32_kernel<<<(n4 + 255) / 256, 256>>>((const float4*)hs, (uint4*)hs_t, n4);
        n4 = QKV_N * HID / 4;
        cvt_tf32_kernel<<<(n4 + 255) / 256, 256>>>((const float4*)w_qkv, (uint4*)wqkv_t, n4);
        n4 = HID * HID / 4;
        cvt_tf32_kernel<<<(n4 + 255) / 256, 256>>>((const float4*)w_dense, (uint4*)wd_t, n4);
    }

    // 1) QKV projection: qkv(tf32 bits) = hs @ w_qkv^T + b_qkv
    gemm_tf32<<<dim3(QKV_N / GBN, ROWS / GBM), 256, GEMM_SMEM_BYTES>>>(
        hs_t, wqkv_t, b_qkv, qkv_buf, ROWS, QKV_N, HID, 1, 1);

    // 2) causal flash attention -> ctx (tf32 bits)
    attn_tf32<<<dim3(S_LEN / 128, NHEAD, BATCH), 256, ATT_BYTES>>>(qkv_buf, ctx_t);

    // 3) dense projection: out(fp32) = ctx @ w_dense^T (skip_bias_add)
    gemm_tf32<<<dim3(HID / GBN, ROWS / GBM), 256, GEMM_SMEM_BYTES>>>(
        ctx_t, wd_t, nullptr, (uint32_t*)out, ROWS, HID, HID, 0, 0);

    // 4) b_dense returned separately -> tail of d_out
    if (out_size >= (int)((size_t)ROWS * HID + HID)) {
        cudaMemcpyAsync(out + (size_t)ROWS * HID, b_dense,
                        HID * sizeof(float), cudaMemcpyDeviceToDevice);
    }
}

// round 7
// speedup vs baseline: 1.0684x; 1.0684x over previous
#include <cuda_runtime.h>
#include <math.h>
#include <stdint.h>

#define S_LEN 2048
#define BATCH 2
#define HID 2048
#define NHEAD 16
#define HDIM 128
#define QKV_N 6144
#define ROWS 4096

// ---------------- scratch (device globals; allocation forbidden) -----------
__device__ uint32_t g_hs_t[(size_t)ROWS * HID];      // tf32 bits of hidden_states
__device__ uint32_t g_wqkv_t[(size_t)QKV_N * HID];   // tf32 bits of w_qkv
__device__ uint32_t g_wd_t[(size_t)HID * HID];       // tf32 bits of w_dense
__device__ uint32_t g_qkv[(size_t)ROWS * QKV_N];     // tf32 bits of qkv
__device__ uint32_t g_ctx_t[(size_t)ROWS * HID];     // tf32 bits of ctx

// ---------------- helpers --------------------------------------------------
__device__ __forceinline__ uint32_t f2tf(float x) {
    uint32_t r; asm("cvt.rna.tf32.f32 %0, %1;" : "=r"(r) : "f"(x)); return r;
}
__device__ __forceinline__ void mma8(float* c, const uint32_t* a, uint32_t b0, uint32_t b1) {
    asm volatile("mma.sync.aligned.m16n8k8.row.col.f32.tf32.tf32.f32 "
        "{%0,%1,%2,%3},{%4,%5,%6,%7},{%8,%9},{%0,%1,%2,%3};"
        : "+f"(c[0]), "+f"(c[1]), "+f"(c[2]), "+f"(c[3])
        : "r"(a[0]), "r"(a[1]), "r"(a[2]), "r"(a[3]), "r"(b0), "r"(b1));
}
__device__ __forceinline__ void cp16(uint32_t saddr, const void* gptr) {
    asm volatile("cp.async.cg.shared.global [%0], [%1], 16;" :: "r"(saddr), "l"(gptr));
}
__device__ __forceinline__ uint32_t smem_u32(const void* p) {
    uint32_t a;
    asm("{ .reg .u64 t; cvta.to.shared.u64 t, %1; cvt.u32.u64 %0, t; }" : "=r"(a) : "l"(p));
    return a;
}

#define MBAR_INIT(addr, cnt) \
    asm volatile("mbarrier.init.shared.b64 [%0], %1;" :: "r"(addr), "r"(cnt) : "memory")
#define MBAR_ARRIVE(addr) \
    asm volatile("mbarrier.arrive.shared.b64 _, [%0];" :: "r"(addr) : "memory")
#define MBAR_ARRIVE_CPASYNC(addr) \
    asm volatile("cp.async.mbarrier.arrive.noinc.shared.b64 [%0];" :: "r"(addr) : "memory")
#define MBAR_WAIT(addr, par) do {                                               \
    uint32_t _done;                                                             \
    asm volatile("{ .reg .pred p; mbarrier.try_wait.parity.acquire.cta.shared::cta.b64 p, [%1], %2; selp.b32 %0,1,0,p; }" \
        : "=r"(_done) : "r"(addr), "r"(par) : "memory");                        \
    while (!_done) {                                                            \
        asm volatile("{ .reg .pred p; mbarrier.try_wait.parity.acquire.cta.shared::cta.b64 p, [%1], %2, 0x989680; selp.b32 %0,1,0,p; }" \
            : "=r"(_done) : "r"(addr), "r"(par) : "memory");                    \
    }                                                                           \
} while (0)

// ---------------- fp32 -> tf32 conversion kernel ---------------------------
__global__ void cvt_tf32_kernel(const float4* __restrict__ in, uint4* __restrict__ out, int n4) {
    int i = blockIdx.x * blockDim.x + threadIdx.x;
    if (i < n4) {
        float4 v = in[i];
        uint4 o;
        o.x = f2tf(v.x); o.y = f2tf(v.y); o.z = f2tf(v.z); o.w = f2tf(v.w);
        out[i] = o;
    }
}

// ---------------- tf32 GEMM: C[m,n] = A[m,:] . B[n,:] (+bias) --------------
// A: [M,K] tf32 bits row-major. B: [N,K] tf32 bits row-major.
// Block 128x128, BK=32, 3-stage ring with mbarrier full/empty pairs —
// NO __syncthreads in the main loop; warps free-run within the 3-stage window.
// 8 warps (2x4), 64x32 warp tiles. out_tf32: write C as tf32 bits.
#define GBM 128
#define GBN 128
#define GBK 32
#define SLD 36
#define TSZ (128 * SLD)
#define GEMM_SMEM_BYTES (3 * 2 * TSZ * 4)       // 110592

__global__ __launch_bounds__(256, 2)
void gemm_tf32(const uint32_t* __restrict__ A, const uint32_t* __restrict__ B,
               const float* __restrict__ bias, uint32_t* __restrict__ C,
               int M, int N, int K, int add_bias, int out_tf32)
{
    extern __shared__ uint32_t sm[];
    __shared__ uint64_t bars[6];                 // full[0..2], empty[0..2]

    const int tid = threadIdx.x;
    const int lane = tid & 31, warp = tid >> 5;
    const int g = lane >> 2, tg = lane & 3;
    const int wm = warp >> 2, wn = warp & 3;     // 2 x 4 warps
    const int m0 = blockIdx.y * GBM, n0 = blockIdx.x * GBN;
    const uint32_t barb = smem_u32(bars);
#define FULLB(s)  (barb + 8u * (uint32_t)(s))
#define EMPTYB(s) (barb + 24u + 8u * (uint32_t)(s))

    if (tid == 0) {
#pragma unroll
        for (int s = 0; s < 3; s++) {
            MBAR_INIT(FULLB(s), 256);
            MBAR_INIT(EMPTYB(s), 256);
        }
    }
    __syncthreads();

    float c[4][4][4];
#pragma unroll
    for (int i = 0; i < 4; i++)
#pragma unroll
        for (int j = 0; j < 4; j++)
#pragma unroll
            for (int q = 0; q < 4; q++) c[i][j][q] = 0.f;

    // each thread loads 4 A-chunks + 4 B-chunks (16B each) per stage
    const int ldRow = tid >> 1;                  // 0..127 (2 chunks per row)
    const int ldCol = (tid & 1) * 4;             // word 0 or 4... (8 words/row over 2 threads)
    auto load_stage = [&](int it) {
        const int buf = it % 3;
        uint32_t* Ab = sm + buf * 2 * TSZ;
        uint32_t ab = (uint32_t)__cvta_generic_to_shared(Ab);
        uint32_t bb = ab + (uint32_t)TSZ * 4;
        const int k0 = it * GBK;
#pragma unroll
        for (int t = 0; t < 4; t++) {            // 128 rows x 8 16B-chunks / 256 thr
            int fid = tid + 256 * t;
            int r = fid >> 3, c4 = (fid & 7) * 4;
            cp16(ab + (uint32_t)(r * SLD + c4) * 4, A + (size_t)(m0 + r) * K + k0 + c4);
            cp16(bb + (uint32_t)(r * SLD + c4) * 4, B + (size_t)(n0 + r) * K + k0 + c4);
        }
        MBAR_ARRIVE_CPASYNC(FULLB(buf));         // async arrive when this thread's cp.asyncs land
    };

    const int NI = K / GBK;
    load_stage(0);
    load_stage(1);

    for (int it = 0; it < NI; it++) {
        const int nx = it + 2;
        if (nx < NI) {
            const int qn = nx % 3, rn = nx / 3;
            if (rn >= 1) MBAR_WAIT(EMPTYB(qn), (uint32_t)((rn - 1) & 1));
            load_stage(nx);
        }
        const int q = it % 3;
        MBAR_WAIT(FULLB(q), (uint32_t)((it / 3) & 1));

        const uint32_t* Ab = sm + q * 2 * TSZ;
        const uint32_t* Bb = Ab + TSZ;
#pragma unroll
        for (int kk = 0; kk < 4; kk++) {
            uint32_t a[4][4];
#pragma unroll
            for (int i = 0; i < 4; i++) {
                const uint32_t* p = Ab + (wm * 64 + i * 16 + g) * SLD + kk * 8 + tg;
                a[i][0] = p[0]; a[i][1] = p[8 * SLD]; a[i][2] = p[4]; a[i][3] = p[8 * SLD + 4];
            }
#pragma unroll
            for (int j = 0; j < 4; j++) {
                const uint32_t* p = Bb + (wn * 32 + j * 8 + g) * SLD + kk * 8 + tg;
                uint32_t b0 = p[0], b1 = p[4];
#pragma unroll
                for (int i = 0; i < 4; i++) mma8(c[i][j], a[i], b0, b1);
            }
        }
        MBAR_ARRIVE(EMPTYB(q));                  // this thread done reading stage q
    }

#pragma unroll
    for (int i = 0; i < 4; i++) {
        int row = m0 + wm * 64 + i * 16 + g;
#pragma unroll
        for (int j = 0; j < 4; j++) {
            int col = n0 + wn * 32 + j * 8 + 2 * tg;
            float b0 = add_bias ? bias[col] : 0.f;
            float b1 = add_bias ? bias[col + 1] : 0.f;
            float v00 = c[i][j][0] + b0, v01 = c[i][j][1] + b1;
            float v10 = c[i][j][2] + b0, v11 = c[i][j][3] + b1;
            uint2 r0, r1;
            if (out_tf32) {
                r0.x = f2tf(v00); r0.y = f2tf(v01);
                r1.x = f2tf(v10); r1.y = f2tf(v11);
            } else {
                r0.x = __float_as_uint(v00); r0.y = __float_as_uint(v01);
                r1.x = __float_as_uint(v10); r1.y = __float_as_uint(v11);
            }
            *(uint2*)(C + (size_t)row * N + col) = r0;
            *(uint2*)(C + (size_t)(row + 8) * N + col) = r1;
        }
    }
#undef FULLB
#undef EMPTYB
}

// ---------------- tf32 flash attention (qkv already tf32 bits) --------------
// Q tile 128 rows (warp owns 16), K/V chunks of 32 rows, double-buffered
// cp.async so the kt+1 load overlaps kt's compute. 8 warps, 1 CTA/SM.
#define AQ_LD 132
#define AK_LD 132
#define AV_LD 136
#define AP_LD 36
#define KCH 32
#define KVBUF (KCH * AK_LD + KCH * AV_LD)
#define ATT_WORDS (128 * AQ_LD + 2 * KVBUF + 128 * AP_LD)
#define ATT_BYTES (ATT_WORDS * 4)               // 154624

__global__ __launch_bounds__(256, 1)
void attn_tf32(const uint32_t* __restrict__ qkv, uint32_t* __restrict__ ctx)
{
    extern __shared__ uint32_t sm[];
    uint32_t* Qs = sm;
    uint32_t* KV = Qs + 128 * AQ_LD;
    uint32_t* Ps = KV + 2 * KVBUF;
    const uint32_t kvb = smem_u32(KV);

    const int tid = threadIdx.x, lane = tid & 31, warp = tid >> 5;
    const int g = lane >> 2, tg = lane & 3;
    const int qt = gridDim.x - 1 - blockIdx.x;   // heavy tiles first
    const int head = blockIdx.y, bb = blockIdx.z;
    const int q0 = qt * 128;
    const size_t hoff = (size_t)head * (3 * HDIM);

    auto load_kv = [&](int kt) {
        const int b = kt & 1;
        const uint32_t kb = kvb + (uint32_t)(b * KVBUF) * 4;
        const uint32_t vb = kb + (uint32_t)(KCH * AK_LD) * 4;
        const int kr0 = kt * KCH;
#pragma unroll
        for (int t = 0; t < 4; t++) {
            int fid = tid + 256 * t;
            int r = fid >> 5, c4 = (fid & 31) * 4;
            const uint32_t* s = qkv + ((size_t)(kr0 + r) * BATCH + bb) * QKV_N + hoff + HDIM + c4;
            cp16(kb + (uint32_t)(r * AK_LD + c4) * 4, s);
            cp16(vb + (uint32_t)(r * AV_LD + c4) * 4, s + HDIM);
        }
        asm volatile("cp.async.commit_group;" ::: "memory");
    };

    {
        uint32_t qsb = smem_u32(Qs);
#pragma unroll
        for (int t = 0; t < 16; t++) {
            int fid = tid + 256 * t;
            int r = fid >> 5, c4 = (fid & 31) * 4;
            const uint32_t* s = qkv + ((size_t)(q0 + r) * BATCH + bb) * QKV_N + hoff + c4;
            cp16(qsb + (uint32_t)(r * AQ_LD + c4) * 4, s);
        }
    }
    load_kv(0);

    float o[16][4];
#pragma unroll
    for (int j = 0; j < 16; j++)
#pragma unroll
        for (int q = 0; q < 4; q++) o[j][q] = 0.f;
    float m0r = -1e30f, m1r = -1e30f, l0r = 0.f, l1r = 0.f;
    const float scale = 0.08838834764831845f;    // 1/sqrt(128)

    const int nkt = 4 * qt + 4;
    for (int kt = 0; kt < nkt; kt++) {
        asm volatile("cp.async.wait_group 0;" ::: "memory");
        __syncthreads();
        if (kt + 1 < nkt) load_kv(kt + 1);

        const int b = kt & 1;
        const uint32_t* Kb = KV + b * KVBUF;
        const uint32_t* Vb = Kb + KCH * AK_LD;
        const int kr0 = kt * KCH;
        const int rowg = q0 + warp * 16 + g;
        const bool active = (kr0 <= q0 + warp * 16 + 15);

        if (active) {
            float s[4][4];
#pragma unroll
            for (int j = 0; j < 4; j++)
#pragma unroll
                for (int q = 0; q < 4; q++) s[j][q] = 0.f;
#pragma unroll
            for (int kk = 0; kk < 16; kk++) {
                uint32_t a[4];
                const uint32_t* qp = Qs + (warp * 16 + g) * AQ_LD + kk * 8 + tg;
                a[0] = qp[0]; a[1] = qp[8 * AQ_LD]; a[2] = qp[4]; a[3] = qp[8 * AQ_LD + 4];
#pragma unroll
                for (int j = 0; j < 4; j++) {
                    const uint32_t* kp = Kb + (j * 8 + g) * AK_LD + kk * 8 + tg;
                    mma8(s[j], a, kp[0], kp[4]);
                }
            }
#pragma unroll
            for (int j = 0; j < 4; j++) {
                int cb = kr0 + j * 8 + 2 * tg;
                s[j][0] = (cb     > rowg)     ? -10000.f : s[j][0] * scale;
                s[j][1] = (cb + 1 > rowg)     ? -10000.f : s[j][1] * scale;
                s[j][2] = (cb     > rowg + 8) ? -10000.f : s[j][2] * scale;
                s[j][3] = (cb + 1 > rowg + 8) ? -10000.f : s[j][3] * scale;
            }
            {
                float ml = -1e30f;
#pragma unroll
                for (int j = 0; j < 4; j++) ml = fmaxf(ml, fmaxf(s[j][0], s[j][1]));
                ml = fmaxf(ml, __shfl_xor_sync(0xffffffffu, ml, 1));
                ml = fmaxf(ml, __shfl_xor_sync(0xffffffffu, ml, 2));
                float mn = fmaxf(m0r, ml);
                float corr = __expf(m0r - mn);
                float ps = 0.f;
#pragma unroll
                for (int j = 0; j < 4; j++) {
                    s[j][0] = __expf(s[j][0] - mn);
                    s[j][1] = __expf(s[j][1] - mn);
                    ps += s[j][0] + s[j][1];
                }
                ps += __shfl_xor_sync(0xffffffffu, ps, 1);
                ps += __shfl_xor_sync(0xffffffffu, ps, 2);
                l0r = l0r * corr + ps; m0r = mn;
#pragma unroll
                for (int j = 0; j < 16; j++) { o[j][0] *= corr; o[j][1] *= corr; }
            }
            {
                float ml = -1e30f;
#pragma unroll
                for (int j = 0; j < 4; j++) ml = fmaxf(ml, fmaxf(s[j][2], s[j][3]));
                ml = fmaxf(ml, __shfl_xor_sync(0xffffffffu, ml, 1));
                ml = fmaxf(ml, __shfl_xor_sync(0xffffffffu, ml, 2));
                float mn = fmaxf(m1r, ml);
                float corr = __expf(m1r - mn);
                float ps = 0.f;
#pragma unroll
                for (int j = 0; j < 4; j++) {
                    s[j][2] = __expf(s[j][2] - mn);
                    s[j][3] = __expf(s[j][3] - mn);
                    ps += s[j][2] + s[j][3];
                }
                ps += __shfl_xor_sync(0xffffffffu, ps, 1);
                ps += __shfl_xor_sync(0xffffffffu, ps, 2);
                l1r = l1r * corr + ps; m1r = mn;
#pragma unroll
                for (int j = 0; j < 16; j++) { o[j][2] *= corr; o[j][3] *= corr; }
            }
#pragma unroll
            for (int j = 0; j < 4; j++) {
                uint32_t* p0 = Ps + (warp * 16 + g) * AP_LD + j * 8 + 2 * tg;
                p0[0] = f2tf(s[j][0]); p0[1] = f2tf(s[j][1]);
                uint32_t* p1 = p0 + 8 * AP_LD;
                p1[0] = f2tf(s[j][2]); p1[1] = f2tf(s[j][3]);
            }
        }
        __syncwarp();
        if (active) {
#pragma unroll
            for (int kk = 0; kk < 4; kk++) {
                uint32_t a[4];
                const uint32_t* pp = Ps + (warp * 16 + g) * AP_LD + kk * 8 + tg;
                a[0] = pp[0]; a[1] = pp[8 * AP_LD]; a[2] = pp[4]; a[3] = pp[8 * AP_LD + 4];
#pragma unroll
                for (int j = 0; j < 16; j++) {
                    const uint32_t* vp = Vb + (kk * 8 + tg) * AV_LD + j * 8 + g;
                    mma8(o[j], a, vp[0], vp[4 * AV_LD]);
                }
            }
        }
    }

    const float i0 = 1.f / l0r, i1 = 1.f / l1r;
    const int r0g = q0 + warp * 16 + g;
#pragma unroll
    for (int j = 0; j < 16; j++) {
        int col = head * HDIM + j * 8 + 2 * tg;
        uint2 v0 = { f2tf(o[j][0] * i0), f2tf(o[j][1] * i0) };
        uint2 v1 = { f2tf(o[j][2] * i1), f2tf(o[j][3] * i1) };
        *(uint2*)(ctx + ((size_t)r0g * BATCH + bb) * HID + col) = v0;
        *(uint2*)(ctx + ((size_t)(r0g + 8) * BATCH + bb) * HID + col) = v1;
    }
}

// ---------------------------------------------------------------------------
extern "C" void kernel_launch(void* const* d_in, const int* in_sizes, int n_in,
                              void* d_out, int out_size)
{
    const float* hs      = (const float*)d_in[0];
    const float* w_qkv   = (const float*)d_in[2];
    const float* b_qkv   = (const float*)d_in[3];
    const float* w_dense = (const float*)d_in[4];
    const float* b_dense = (const float*)d_in[5];
    float* out = (float*)d_out;

    uint32_t *hs_t, *wqkv_t, *wd_t, *ctx_t, *qkv_buf;
    cudaGetSymbolAddress((void**)&hs_t, g_hs_t);
    cudaGetSymbolAddress((void**)&wqkv_t, g_wqkv_t);
    cudaGetSymbolAddress((void**)&wd_t, g_wd_t);
    cudaGetSymbolAddress((void**)&qkv_buf, g_qkv);
    cudaGetSymbolAddress((void**)&ctx_t, g_ctx_t);

    cudaFuncSetAttribute(gemm_tf32, cudaFuncAttributeMaxDynamicSharedMemorySize, GEMM_SMEM_BYTES);
    cudaFuncSetAttribute(attn_tf32, cudaFuncAttributeMaxDynamicSharedMemorySize, ATT_BYTES);

    // 0) pre-round GEMM operands to tf32 (rna)
    {
        int n4;
        n4 = ROWS * HID / 4;
        cvt_tf32_kernel<<<(n4 + 255) / 256, 256>>>((const float4*)hs, (uint4*)hs_t, n4);
        n4 = QKV_N * HID / 4;
        cvt_tf32_kernel<<<(n4 + 255) / 256, 256>>>((const float4*)w_qkv, (uint4*)wqkv_t, n4);
        n4 = HID * HID / 4;
        cvt_tf32_kernel<<<(n4 + 255) / 256, 256>>>((const float4*)w_dense, (uint4*)wd_t, n4);
    }

    // 1) QKV projection: qkv(tf32 bits) = hs @ w_qkv^T + b_qkv
    gemm_tf32<<<dim3(QKV_N / GBN, ROWS / GBM), 256, GEMM_SMEM_BYTES>>>(
        hs_t, wqkv_t, b_qkv, qkv_buf, ROWS, QKV_N, HID, 1, 1);

    // 2) causal flash attention -> ctx (tf32 bits)
    attn_tf32<<<dim3(S_LEN / 128, NHEAD, BATCH), 256, ATT_BYTES>>>(qkv_buf, ctx_t);

    // 3) dense projection: out(fp32) = ctx @ w_dense^T (skip_bias_add)
    gemm_tf32<<<dim3(HID / GBN, ROWS / GBM), 256, GEMM_SMEM_BYTES>>>(
        ctx_t, wd_t, nullptr, (uint32_t*)out, ROWS, HID, HID, 0, 0);

    // 4) b_dense returned separately -> tail of d_out
    if (out_size >= (int)((size_t)ROWS * HID + HID)) {
        cudaMemcpyAsync(out + (size_t)ROWS * HID, b_dense,
                        HID * sizeof(float), cudaMemcpyDeviceToDevice);
    }
}

// round 8
// speedup vs baseline: 1.1104x; 1.0393x over previous
#include <cuda_runtime.h>
#include <math.h>
#include <stdint.h>

#define S_LEN 2048
#define BATCH 2
#define HID 2048
#define NHEAD 16
#define HDIM 128
#define QKV_N 6144
#define ROWS 4096

// ---------------- scratch (device globals; allocation forbidden) -----------
__device__ uint32_t g_hs_t[(size_t)ROWS * HID];      // tf32 bits of hidden_states
__device__ uint32_t g_wqkv_t[(size_t)QKV_N * HID];   // tf32 bits of w_qkv
__device__ uint32_t g_wd_t[(size_t)HID * HID];       // tf32 bits of w_dense
__device__ uint32_t g_qkv[(size_t)ROWS * QKV_N];     // tf32 bits of qkv
__device__ uint32_t g_ctx_t[(size_t)ROWS * HID];     // tf32 bits of ctx

// ---------------- helpers --------------------------------------------------
__device__ __forceinline__ uint32_t f2tf(float x) {
    uint32_t r; asm("cvt.rna.tf32.f32 %0, %1;" : "=r"(r) : "f"(x)); return r;
}
__device__ __forceinline__ void mma8(float* c, const uint32_t* a, uint32_t b0, uint32_t b1) {
    asm volatile("mma.sync.aligned.m16n8k8.row.col.f32.tf32.tf32.f32 "
        "{%0,%1,%2,%3},{%4,%5,%6,%7},{%8,%9},{%0,%1,%2,%3};"
        : "+f"(c[0]), "+f"(c[1]), "+f"(c[2]), "+f"(c[3])
        : "r"(a[0]), "r"(a[1]), "r"(a[2]), "r"(a[3]), "r"(b0), "r"(b1));
}
__device__ __forceinline__ void cp16(uint32_t saddr, const void* gptr) {
    asm volatile("cp.async.cg.shared.global [%0], [%1], 16;" :: "r"(saddr), "l"(gptr));
}
__device__ __forceinline__ uint32_t smem_u32(const void* p) {
    uint32_t a;
    asm("{ .reg .u64 t; cvta.to.shared.u64 t, %1; cvt.u32.u64 %0, t; }" : "=r"(a) : "l"(p));
    return a;
}

#define MBAR_INIT(addr, cnt) \
    asm volatile("mbarrier.init.shared.b64 [%0], %1;" :: "r"(addr), "r"(cnt) : "memory")
#define MBAR_ARRIVE(addr) \
    asm volatile("mbarrier.arrive.shared.b64 _, [%0];" :: "r"(addr) : "memory")
#define MBAR_ARRIVE_CPASYNC(addr) \
    asm volatile("cp.async.mbarrier.arrive.noinc.shared.b64 [%0];" :: "r"(addr) : "memory")
#define MBAR_WAIT(addr, par) do {                                               \
    uint32_t _done;                                                             \
    asm volatile("{ .reg .pred p; mbarrier.try_wait.parity.acquire.cta.shared::cta.b64 p, [%1], %2; selp.b32 %0,1,0,p; }" \
        : "=r"(_done) : "r"(addr), "r"(par) : "memory");                        \
    while (!_done) {                                                            \
        asm volatile("{ .reg .pred p; mbarrier.try_wait.parity.acquire.cta.shared::cta.b64 p, [%1], %2, 0x989680; selp.b32 %0,1,0,p; }" \
            : "=r"(_done) : "r"(addr), "r"(par) : "memory");                    \
    }                                                                           \
} while (0)

// ---------------- fp32 -> tf32 conversion kernel ---------------------------
__global__ void cvt_tf32_kernel(const float4* __restrict__ in, uint4* __restrict__ out, int n4) {
    int i = blockIdx.x * blockDim.x + threadIdx.x;
    if (i < n4) {
        float4 v = in[i];
        uint4 o;
        o.x = f2tf(v.x); o.y = f2tf(v.y); o.z = f2tf(v.z); o.w = f2tf(v.w);
        out[i] = o;
    }
}

// ---------------- tf32 GEMM: C[m,n] = A[m,:] . B[n,:] (+bias) --------------
// A: [M,K] tf32 bits row-major. B: [N,K] tf32 bits row-major.
// CTA 128x128, BK=32, 128 threads = 4 warps in 2x2, each a 64x64 warp tile
// (halves smem fragment traffic per MAC vs 64x32 tiles). 3-stage mbarrier
// ring, no __syncthreads in the main loop. 2 CTAs/SM.
#define GBM 128
#define GBN 128
#define GBK 32
#define SLD 36
#define TSZ (128 * SLD)
#define GEMM_SMEM_BYTES (3 * 2 * TSZ * 4)       // 110592
#define GTHREADS 128

__global__ __launch_bounds__(GTHREADS, 2)
void gemm_tf32(const uint32_t* __restrict__ A, const uint32_t* __restrict__ B,
               const float* __restrict__ bias, uint32_t* __restrict__ C,
               int M, int N, int K, int add_bias, int out_tf32)
{
    extern __shared__ uint32_t sm[];
    __shared__ uint64_t bars[6];                 // full[0..2], empty[0..2]

    const int tid = threadIdx.x;
    const int lane = tid & 31, warp = tid >> 5;
    const int g = lane >> 2, tg = lane & 3;
    const int wm = warp >> 1, wn = warp & 1;     // 2 x 2 warps
    const int m0 = blockIdx.y * GBM, n0 = blockIdx.x * GBN;
    const uint32_t barb = smem_u32(bars);
#define FULLB(s)  (barb + 8u * (uint32_t)(s))
#define EMPTYB(s) (barb + 24u + 8u * (uint32_t)(s))

    if (tid == 0) {
#pragma unroll
        for (int s = 0; s < 3; s++) {
            MBAR_INIT(FULLB(s), GTHREADS);
            MBAR_INIT(EMPTYB(s), GTHREADS);
        }
    }
    __syncthreads();

    float c[4][8][4];                            // 64x64 warp tile: 128 regs
#pragma unroll
    for (int i = 0; i < 4; i++)
#pragma unroll
        for (int j = 0; j < 8; j++)
#pragma unroll
            for (int q = 0; q < 4; q++) c[i][j][q] = 0.f;

    auto load_stage = [&](int it) {
        const int buf = it % 3;
        uint32_t ab = (uint32_t)__cvta_generic_to_shared(sm + buf * 2 * TSZ);
        uint32_t bb = ab + (uint32_t)TSZ * 4;
        const int k0 = it * GBK;
#pragma unroll
        for (int t = 0; t < 8; t++) {            // 128 rows x 8 16B-chunks / 128 thr
            int fid = tid + GTHREADS * t;
            int r = fid >> 3, c4 = (fid & 7) * 4;
            cp16(ab + (uint32_t)(r * SLD + c4) * 4, A + (size_t)(m0 + r) * K + k0 + c4);
            cp16(bb + (uint32_t)(r * SLD + c4) * 4, B + (size_t)(n0 + r) * K + k0 + c4);
        }
        MBAR_ARRIVE_CPASYNC(FULLB(buf));
    };

    const int NI = K / GBK;
    load_stage(0);
    load_stage(1);

    for (int it = 0; it < NI; it++) {
        const int nx = it + 2;
        if (nx < NI) {
            const int qn = nx % 3, rn = nx / 3;
            if (rn >= 1) MBAR_WAIT(EMPTYB(qn), (uint32_t)((rn - 1) & 1));
            load_stage(nx);
        }
        const int q = it % 3;
        MBAR_WAIT(FULLB(q), (uint32_t)((it / 3) & 1));

        const uint32_t* Ab = sm + q * 2 * TSZ;
        const uint32_t* Bb = Ab + TSZ;
#pragma unroll
        for (int kk = 0; kk < 4; kk++) {
            uint32_t a[4][4];
#pragma unroll
            for (int i = 0; i < 4; i++) {
                const uint32_t* p = Ab + (wm * 64 + i * 16 + g) * SLD + kk * 8 + tg;
                a[i][0] = p[0]; a[i][1] = p[8 * SLD]; a[i][2] = p[4]; a[i][3] = p[8 * SLD + 4];
            }
#pragma unroll
            for (int j = 0; j < 8; j++) {
                const uint32_t* p = Bb + (wn * 64 + j * 8 + g) * SLD + kk * 8 + tg;
                uint32_t b0 = p[0], b1 = p[4];
#pragma unroll
                for (int i = 0; i < 4; i++) mma8(c[i][j], a[i], b0, b1);
            }
        }
        MBAR_ARRIVE(EMPTYB(q));
    }

#pragma unroll
    for (int i = 0; i < 4; i++) {
        int row = m0 + wm * 64 + i * 16 + g;
#pragma unroll
        for (int j = 0; j < 8; j++) {
            int col = n0 + wn * 64 + j * 8 + 2 * tg;
            float b0 = add_bias ? bias[col] : 0.f;
            float b1 = add_bias ? bias[col + 1] : 0.f;
            float v00 = c[i][j][0] + b0, v01 = c[i][j][1] + b1;
            float v10 = c[i][j][2] + b0, v11 = c[i][j][3] + b1;
            uint2 r0, r1;
            if (out_tf32) {
                r0.x = f2tf(v00); r0.y = f2tf(v01);
                r1.x = f2tf(v10); r1.y = f2tf(v11);
            } else {
                r0.x = __float_as_uint(v00); r0.y = __float_as_uint(v01);
                r1.x = __float_as_uint(v10); r1.y = __float_as_uint(v11);
            }
            *(uint2*)(C + (size_t)row * N + col) = r0;
            *(uint2*)(C + (size_t)(row + 8) * N + col) = r1;
        }
    }
#undef FULLB
#undef EMPTYB
}

// ---------------- tf32 flash attention (qkv already tf32 bits) --------------
// Q tile 128 rows (warp owns 16), K/V chunks of 32 rows, double-buffered
// cp.async so the kt+1 load overlaps kt's compute. 8 warps, 1 CTA/SM.
#define AQ_LD 132
#define AK_LD 132
#define AV_LD 136
#define AP_LD 36
#define KCH 32
#define KVBUF (KCH * AK_LD + KCH * AV_LD)
#define ATT_WORDS (128 * AQ_LD + 2 * KVBUF + 128 * AP_LD)
#define ATT_BYTES (ATT_WORDS * 4)               // 154624

__global__ __launch_bounds__(256, 1)
void attn_tf32(const uint32_t* __restrict__ qkv, uint32_t* __restrict__ ctx)
{
    extern __shared__ uint32_t sm[];
    uint32_t* Qs = sm;
    uint32_t* KV = Qs + 128 * AQ_LD;
    uint32_t* Ps = KV + 2 * KVBUF;
    const uint32_t kvb = smem_u32(KV);

    const int tid = threadIdx.x, lane = tid & 31, warp = tid >> 5;
    const int g = lane >> 2, tg = lane & 3;
    const int qt = gridDim.x - 1 - blockIdx.x;   // heavy tiles first
    const int head = blockIdx.y, bb = blockIdx.z;
    const int q0 = qt * 128;
    const size_t hoff = (size_t)head * (3 * HDIM);

    auto load_kv = [&](int kt) {
        const int b = kt & 1;
        const uint32_t kb = kvb + (uint32_t)(b * KVBUF) * 4;
        const uint32_t vb = kb + (uint32_t)(KCH * AK_LD) * 4;
        const int kr0 = kt * KCH;
#pragma unroll
        for (int t = 0; t < 4; t++) {
            int fid = tid + 256 * t;
            int r = fid >> 5, c4 = (fid & 31) * 4;
            const uint32_t* s = qkv + ((size_t)(kr0 + r) * BATCH + bb) * QKV_N + hoff + HDIM + c4;
            cp16(kb + (uint32_t)(r * AK_LD + c4) * 4, s);
            cp16(vb + (uint32_t)(r * AV_LD + c4) * 4, s + HDIM);
        }
        asm volatile("cp.async.commit_group;" ::: "memory");
    };

    {
        uint32_t qsb = smem_u32(Qs);
#pragma unroll
        for (int t = 0; t < 16; t++) {
            int fid = tid + 256 * t;
            int r = fid >> 5, c4 = (fid & 31) * 4;
            const uint32_t* s = qkv + ((size_t)(q0 + r) * BATCH + bb) * QKV_N + hoff + c4;
            cp16(qsb + (uint32_t)(r * AQ_LD + c4) * 4, s);
        }
    }
    load_kv(0);

    float o[16][4];
#pragma unroll
    for (int j = 0; j < 16; j++)
#pragma unroll
        for (int q = 0; q < 4; q++) o[j][q] = 0.f;
    float m0r = -1e30f, m1r = -1e30f, l0r = 0.f, l1r = 0.f;
    const float scale = 0.08838834764831845f;    // 1/sqrt(128)

    const int nkt = 4 * qt + 4;
    for (int kt = 0; kt < nkt; kt++) {
        asm volatile("cp.async.wait_group 0;" ::: "memory");
        __syncthreads();
        if (kt + 1 < nkt) load_kv(kt + 1);

        const int b = kt & 1;
        const uint32_t* Kb = KV + b * KVBUF;
        const uint32_t* Vb = Kb + KCH * AK_LD;
        const int kr0 = kt * KCH;
        const int rowg = q0 + warp * 16 + g;
        const bool active = (kr0 <= q0 + warp * 16 + 15);

        if (active) {
            float s[4][4];
#pragma unroll
            for (int j = 0; j < 4; j++)
#pragma unroll
                for (int q = 0; q < 4; q++) s[j][q] = 0.f;
#pragma unroll
            for (int kk = 0; kk < 16; kk++) {
                uint32_t a[4];
                const uint32_t* qp = Qs + (warp * 16 + g) * AQ_LD + kk * 8 + tg;
                a[0] = qp[0]; a[1] = qp[8 * AQ_LD]; a[2] = qp[4]; a[3] = qp[8 * AQ_LD + 4];
#pragma unroll
                for (int j = 0; j < 4; j++) {
                    const uint32_t* kp = Kb + (j * 8 + g) * AK_LD + kk * 8 + tg;
                    mma8(s[j], a, kp[0], kp[4]);
                }
            }
#pragma unroll
            for (int j = 0; j < 4; j++) {
                int cb = kr0 + j * 8 + 2 * tg;
                s[j][0] = (cb     > rowg)     ? -10000.f : s[j][0] * scale;
                s[j][1] = (cb + 1 > rowg)     ? -10000.f : s[j][1] * scale;
                s[j][2] = (cb     > rowg + 8) ? -10000.f : s[j][2] * scale;
                s[j][3] = (cb + 1 > rowg + 8) ? -10000.f : s[j][3] * scale;
            }
            {
                float ml = -1e30f;
#pragma unroll
                for (int j = 0; j < 4; j++) ml = fmaxf(ml, fmaxf(s[j][0], s[j][1]));
                ml = fmaxf(ml, __shfl_xor_sync(0xffffffffu, ml, 1));
                ml = fmaxf(ml, __shfl_xor_sync(0xffffffffu, ml, 2));
                float mn = fmaxf(m0r, ml);
                float corr = __expf(m0r - mn);
                float ps = 0.f;
#pragma unroll
                for (int j = 0; j < 4; j++) {
                    s[j][0] = __expf(s[j][0] - mn);
                    s[j][1] = __expf(s[j][1] - mn);
                    ps += s[j][0] + s[j][1];
                }
                ps += __shfl_xor_sync(0xffffffffu, ps, 1);
                ps += __shfl_xor_sync(0xffffffffu, ps, 2);
                l0r = l0r * corr + ps; m0r = mn;
#pragma unroll
                for (int j = 0; j < 16; j++) { o[j][0] *= corr; o[j][1] *= corr; }
            }
            {
                float ml = -1e30f;
#pragma unroll
                for (int j = 0; j < 4; j++) ml = fmaxf(ml, fmaxf(s[j][2], s[j][3]));
                ml = fmaxf(ml, __shfl_xor_sync(0xffffffffu, ml, 1));
                ml = fmaxf(ml, __shfl_xor_sync(0xffffffffu, ml, 2));
                float mn = fmaxf(m1r, ml);
                float corr = __expf(m1r - mn);
                float ps = 0.f;
#pragma unroll
                for (int j = 0; j < 4; j++) {
                    s[j][2] = __expf(s[j][2] - mn);
                    s[j][3] = __expf(s[j][3] - mn);
                    ps += s[j][2] + s[j][3];
                }
                ps += __shfl_xor_sync(0xffffffffu, ps, 1);
                ps += __shfl_xor_sync(0xffffffffu, ps, 2);
                l1r = l1r * corr + ps; m1r = mn;
#pragma unroll
                for (int j = 0; j < 16; j++) { o[j][2] *= corr; o[j][3] *= corr; }
            }
#pragma unroll
            for (int j = 0; j < 4; j++) {
                uint32_t* p0 = Ps + (warp * 16 + g) * AP_LD + j * 8 + 2 * tg;
                p0[0] = f2tf(s[j][0]); p0[1] = f2tf(s[j][1]);
                uint32_t* p1 = p0 + 8 * AP_LD;
                p1[0] = f2tf(s[j][2]); p1[1] = f2tf(s[j][3]);
            }
        }
        __syncwarp();
        if (active) {
#pragma unroll
            for (int kk = 0; kk < 4; kk++) {
                uint32_t a[4];
                const uint32_t* pp = Ps + (warp * 16 + g) * AP_LD + kk * 8 + tg;
                a[0] = pp[0]; a[1] = pp[8 * AP_LD]; a[2] = pp[4]; a[3] = pp[8 * AP_LD + 4];
#pragma unroll
                for (int j = 0; j < 16; j++) {
                    const uint32_t* vp = Vb + (kk * 8 + tg) * AV_LD + j * 8 + g;
                    mma8(o[j], a, vp[0], vp[4 * AV_LD]);
                }
            }
        }
    }

    const float i0 = 1.f / l0r, i1 = 1.f / l1r;
    const int r0g = q0 + warp * 16 + g;
#pragma unroll
    for (int j = 0; j < 16; j++) {
        int col = head * HDIM + j * 8 + 2 * tg;
        uint2 v0 = { f2tf(o[j][0] * i0), f2tf(o[j][1] * i0) };
        uint2 v1 = { f2tf(o[j][2] * i1), f2tf(o[j][3] * i1) };
        *(uint2*)(ctx + ((size_t)r0g * BATCH + bb) * HID + col) = v0;
        *(uint2*)(ctx + ((size_t)(r0g + 8) * BATCH + bb) * HID + col) = v1;
    }
}

// ---------------------------------------------------------------------------
extern "C" void kernel_launch(void* const* d_in, const int* in_sizes, int n_in,
                              void* d_out, int out_size)
{
    const float* hs      = (const float*)d_in[0];
    const float* w_qkv   = (const float*)d_in[2];
    const float* b_qkv   = (const float*)d_in[3];
    const float* w_dense = (const float*)d_in[4];
    const float* b_dense = (const float*)d_in[5];
    float* out = (float*)d_out;

    uint32_t *hs_t, *wqkv_t, *wd_t, *ctx_t, *qkv_buf;
    cudaGetSymbolAddress((void**)&hs_t, g_hs_t);
    cudaGetSymbolAddress((void**)&wqkv_t, g_wqkv_t);
    cudaGetSymbolAddress((void**)&wd_t, g_wd_t);
    cudaGetSymbolAddress((void**)&qkv_buf, g_qkv);
    cudaGetSymbolAddress((void**)&ctx_t, g_ctx_t);

    cudaFuncSetAttribute(gemm_tf32, cudaFuncAttributeMaxDynamicSharedMemorySize, GEMM_SMEM_BYTES);
    cudaFuncSetAttribute(attn_tf32, cudaFuncAttributeMaxDynamicSharedMemorySize, ATT_BYTES);

    // 0) pre-round GEMM operands to tf32 (rna)
    {
        int n4;
        n4 = ROWS * HID / 4;
        cvt_tf32_kernel<<<(n4 + 255) / 256, 256>>>((const float4*)hs, (uint4*)hs_t, n4);
        n4 = QKV_N * HID / 4;
        cvt_tf32_kernel<<<(n4 + 255) / 256, 256>>>((const float4*)w_qkv, (uint4*)wqkv_t, n4);
        n4 = HID * HID / 4;
        cvt_tf32_kernel<<<(n4 + 255) / 256, 256>>>((const float4*)w_dense, (uint4*)wd_t, n4);
    }

    // 1) QKV projection: qkv(tf32 bits) = hs @ w_qkv^T + b_qkv
    gemm_tf32<<<dim3(QKV_N / GBN, ROWS / GBM), GTHREADS, GEMM_SMEM_BYTES>>>(
        hs_t, wqkv_t, b_qkv, qkv_buf, ROWS, QKV_N, HID, 1, 1);

    // 2) causal flash attention -> ctx (tf32 bits)
    attn_tf32<<<dim3(S_LEN / 128, NHEAD, BATCH), 256, ATT_BYTES>>>(qkv_buf, ctx_t);

    // 3) dense projection: out(fp32) = ctx @ w_dense^T (skip_bias_add)
    gemm_tf32<<<dim3(HID / GBN, ROWS / GBM), GTHREADS, GEMM_SMEM_BYTES>>>(
        ctx_t, wd_t, nullptr, (uint32_t*)out, ROWS, HID, HID, 0, 0);

    // 4) b_dense returned separately -> tail of d_out
    if (out_size >= (int)((size_t)ROWS * HID + HID)) {
        cudaMemcpyAsync(out + (size_t)ROWS * HID, b_dense,
                        HID * sizeof(float), cudaMemcpyDeviceToDevice);
    }
}

// round 9
// speedup vs baseline: 1.1765x; 1.0595x over previous
#include <cuda_runtime.h>
#include <math.h>
#include <stdint.h>

#define S_LEN 2048
#define BATCH 2
#define HID 2048
#define NHEAD 16
#define HDIM 128
#define QKV_N 6144
#define ROWS 4096

// ---------------- scratch (device globals; allocation forbidden) -----------
__device__ uint32_t g_hs_t[(size_t)ROWS * HID];      // tf32 bits of hidden_states
__device__ uint32_t g_wqkv_t[(size_t)QKV_N * HID];   // tf32 bits of w_qkv
__device__ uint32_t g_wd_t[(size_t)HID * HID];       // tf32 bits of w_dense
__device__ uint32_t g_qkv[(size_t)ROWS * QKV_N];     // tf32 bits of qkv
__device__ uint32_t g_ctx_t[(size_t)ROWS * HID];     // tf32 bits of ctx

// ---------------- helpers --------------------------------------------------
__device__ __forceinline__ uint32_t f2tf(float x) {
    uint32_t r; asm("cvt.rna.tf32.f32 %0, %1;" : "=r"(r) : "f"(x)); return r;
}
__device__ __forceinline__ void mma8(float* c, const uint32_t* a, uint32_t b0, uint32_t b1) {
    asm volatile("mma.sync.aligned.m16n8k8.row.col.f32.tf32.tf32.f32 "
        "{%0,%1,%2,%3},{%4,%5,%6,%7},{%8,%9},{%0,%1,%2,%3};"
        : "+f"(c[0]), "+f"(c[1]), "+f"(c[2]), "+f"(c[3])
        : "r"(a[0]), "r"(a[1]), "r"(a[2]), "r"(a[3]), "r"(b0), "r"(b1));
}
__device__ __forceinline__ void ldsm4(uint32_t* r, uint32_t addr) {
    asm volatile("ldmatrix.sync.aligned.m8n8.x4.shared.b16 {%0,%1,%2,%3}, [%4];"
        : "=r"(r[0]), "=r"(r[1]), "=r"(r[2]), "=r"(r[3]) : "r"(addr));
}
__device__ __forceinline__ void cp16(uint32_t saddr, const void* gptr) {
    asm volatile("cp.async.cg.shared.global [%0], [%1], 16;" :: "r"(saddr), "l"(gptr));
}
__device__ __forceinline__ uint32_t smem_u32(const void* p) {
    uint32_t a;
    asm("{ .reg .u64 t; cvta.to.shared.u64 t, %1; cvt.u32.u64 %0, t; }" : "=r"(a) : "l"(p));
    return a;
}

#define MBAR_INIT(addr, cnt) \
    asm volatile("mbarrier.init.shared.b64 [%0], %1;" :: "r"(addr), "r"(cnt) : "memory")
#define MBAR_ARRIVE(addr) \
    asm volatile("mbarrier.arrive.shared.b64 _, [%0];" :: "r"(addr) : "memory")
#define MBAR_ARRIVE_CPASYNC(addr) \
    asm volatile("cp.async.mbarrier.arrive.noinc.shared.b64 [%0];" :: "r"(addr) : "memory")
#define MBAR_WAIT(addr, par) do {                                               \
    uint32_t _done;                                                             \
    asm volatile("{ .reg .pred p; mbarrier.try_wait.parity.acquire.cta.shared::cta.b64 p, [%1], %2; selp.b32 %0,1,0,p; }" \
        : "=r"(_done) : "r"(addr), "r"(par) : "memory");                        \
    while (!_done) {                                                            \
        asm volatile("{ .reg .pred p; mbarrier.try_wait.parity.acquire.cta.shared::cta.b64 p, [%1], %2, 0x989680; selp.b32 %0,1,0,p; }" \
            : "=r"(_done) : "r"(addr), "r"(par) : "memory");                    \
    }                                                                           \
} while (0)

// ---------------- fp32 -> tf32 conversion kernel ---------------------------
__global__ void cvt_tf32_kernel(const float4* __restrict__ in, uint4* __restrict__ out, int n4) {
    int i = blockIdx.x * blockDim.x + threadIdx.x;
    if (i < n4) {
        float4 v = in[i];
        uint4 o;
        o.x = f2tf(v.x); o.y = f2tf(v.y); o.z = f2tf(v.z); o.w = f2tf(v.w);
        out[i] = o;
    }
}

// ---------------- tf32 GEMM: C[m,n] = A[m,:] . B[n,:] (+bias) --------------
// CTA 128x128, BK=32, 128 threads = 2x2 warps with 64x64 tiles. 3-stage
// mbarrier ring. Fragment loads via ldmatrix.x4 (8 LDSM/kk vs 32 LDS).
#define GBM 128
#define GBN 128
#define GBK 32
#define SLD 36
#define TSZ (128 * SLD)
#define GEMM_SMEM_BYTES (3 * 2 * TSZ * 4)       // 110592
#define GTHREADS 128

__global__ __launch_bounds__(GTHREADS, 2)
void gemm_tf32(const uint32_t* __restrict__ A, const uint32_t* __restrict__ B,
               const float* __restrict__ bias, uint32_t* __restrict__ C,
               int M, int N, int K, int add_bias, int out_tf32)
{
    extern __shared__ uint32_t sm[];
    __shared__ uint64_t bars[6];                 // full[0..2], empty[0..2]

    const int tid = threadIdx.x;
    const int lane = tid & 31, warp = tid >> 5;
    const int g = lane >> 2, tg = lane & 3;
    const int wm = warp >> 1, wn = warp & 1;     // 2 x 2 warps
    const int m0 = blockIdx.y * GBM, n0 = blockIdx.x * GBN;
    const uint32_t smb = smem_u32(sm);
    const uint32_t barb = smem_u32(bars);
#define FULLB(s)  (barb + 8u * (uint32_t)(s))
#define EMPTYB(s) (barb + 24u + 8u * (uint32_t)(s))

    if (tid == 0) {
#pragma unroll
        for (int s = 0; s < 3; s++) {
            MBAR_INIT(FULLB(s), GTHREADS);
            MBAR_INIT(EMPTYB(s), GTHREADS);
        }
    }
    __syncthreads();

    // ldmatrix per-thread row offsets (bytes, stage-relative)
    // A fragment (m16k8): matrices {rows 0-7, rows 8-15, rows 0-7 w+4, rows 8-15 w+4}
    const uint32_t aRowOff = (uint32_t)(((wm * 64 + (lane & 15)) * SLD + (lane >> 4) * 4) * 4);
    // B fragment pair (two n8k8 tiles): {rows j0 w0, rows j0 w+4, rows j1 w0, rows j1 w+4}
    const uint32_t bRowOff = (uint32_t)(((wn * 64 + ((lane >> 4) & 1) * 8 + (lane & 7)) * SLD
                                         + ((lane >> 3) & 1) * 4) * 4);

    float c[4][8][4];                            // 64x64 warp tile
#pragma unroll
    for (int i = 0; i < 4; i++)
#pragma unroll
        for (int j = 0; j < 8; j++)
#pragma unroll
            for (int q = 0; q < 4; q++) c[i][j][q] = 0.f;

    auto load_stage = [&](int it) {
        const int buf = it % 3;
        uint32_t ab = smb + (uint32_t)(buf * 2 * TSZ) * 4;
        uint32_t bb = ab + (uint32_t)TSZ * 4;
        const int k0 = it * GBK;
#pragma unroll
        for (int t = 0; t < 8; t++) {            // 128 rows x 8 16B-chunks / 128 thr
            int fid = tid + GTHREADS * t;
            int r = fid >> 3, c4 = (fid & 7) * 4;
            cp16(ab + (uint32_t)(r * SLD + c4) * 4, A + (size_t)(m0 + r) * K + k0 + c4);
            cp16(bb + (uint32_t)(r * SLD + c4) * 4, B + (size_t)(n0 + r) * K + k0 + c4);
        }
        MBAR_ARRIVE_CPASYNC(FULLB(buf));
    };

    const int NI = K / GBK;
    load_stage(0);
    load_stage(1);

    for (int it = 0; it < NI; it++) {
        const int nx = it + 2;
        if (nx < NI) {
            const int qn = nx % 3, rn = nx / 3;
            if (rn >= 1) MBAR_WAIT(EMPTYB(qn), (uint32_t)((rn - 1) & 1));
            load_stage(nx);
        }
        const int q = it % 3;
        MBAR_WAIT(FULLB(q), (uint32_t)((it / 3) & 1));

        const uint32_t aBase = smb + (uint32_t)(q * 2 * TSZ) * 4 + aRowOff;
        const uint32_t bBase = smb + (uint32_t)(q * 2 * TSZ + TSZ) * 4 + bRowOff;
#pragma unroll
        for (int kk = 0; kk < 4; kk++) {
            uint32_t a[4][4], bv[4][4];
#pragma unroll
            for (int i = 0; i < 4; i++)
                ldsm4(a[i], aBase + (uint32_t)(i * 16 * SLD) * 4 + kk * 32);
#pragma unroll
            for (int jp = 0; jp < 4; jp++)
                ldsm4(bv[jp], bBase + (uint32_t)(jp * 16 * SLD) * 4 + kk * 32);
#pragma unroll
            for (int jp = 0; jp < 4; jp++)
#pragma unroll
                for (int i = 0; i < 4; i++) {
                    mma8(c[i][2 * jp],     a[i], bv[jp][0], bv[jp][1]);
                    mma8(c[i][2 * jp + 1], a[i], bv[jp][2], bv[jp][3]);
                }
        }
        MBAR_ARRIVE(EMPTYB(q));
    }

#pragma unroll
    for (int i = 0; i < 4; i++) {
        int row = m0 + wm * 64 + i * 16 + g;
#pragma unroll
        for (int j = 0; j < 8; j++) {
            int col = n0 + wn * 64 + j * 8 + 2 * tg;
            float b0 = add_bias ? bias[col] : 0.f;
            float b1 = add_bias ? bias[col + 1] : 0.f;
            float v00 = c[i][j][0] + b0, v01 = c[i][j][1] + b1;
            float v10 = c[i][j][2] + b0, v11 = c[i][j][3] + b1;
            uint2 r0, r1;
            if (out_tf32) {
                r0.x = f2tf(v00); r0.y = f2tf(v01);
                r1.x = f2tf(v10); r1.y = f2tf(v11);
            } else {
                r0.x = __float_as_uint(v00); r0.y = __float_as_uint(v01);
                r1.x = __float_as_uint(v10); r1.y = __float_as_uint(v11);
            }
            *(uint2*)(C + (size_t)row * N + col) = r0;
            *(uint2*)(C + (size_t)(row + 8) * N + col) = r1;
        }
    }
#undef FULLB
#undef EMPTYB
}

// ---------------- tf32 flash attention (qkv already tf32 bits) --------------
// Q tile 128 rows (warp owns 16), K/V chunks of 32 rows, double-buffered.
// Q/K and P fragments via ldmatrix; V stays scalar (transposed access).
#define AQ_LD 132
#define AK_LD 132
#define AV_LD 136
#define AP_LD 36
#define KCH 32
#define KVBUF (KCH * AK_LD + KCH * AV_LD)
#define ATT_WORDS (128 * AQ_LD + 2 * KVBUF + 128 * AP_LD)
#define ATT_BYTES (ATT_WORDS * 4)               // 154624

__global__ __launch_bounds__(256, 1)
void attn_tf32(const uint32_t* __restrict__ qkv, uint32_t* __restrict__ ctx)
{
    extern __shared__ uint32_t sm[];
    uint32_t* Qs = sm;
    uint32_t* KV = Qs + 128 * AQ_LD;
    uint32_t* Ps = KV + 2 * KVBUF;
    const uint32_t kvb = smem_u32(KV);

    const int tid = threadIdx.x, lane = tid & 31, warp = tid >> 5;
    const int g = lane >> 2, tg = lane & 3;
    const int qt = gridDim.x - 1 - blockIdx.x;   // heavy tiles first
    const int head = blockIdx.y, bb = blockIdx.z;
    const int q0 = qt * 128;
    const size_t hoff = (size_t)head * (3 * HDIM);

    // ldmatrix row offsets
    const uint32_t qRowOff = (uint32_t)(((warp * 16 + (lane & 15)) * AQ_LD + (lane >> 4) * 4) * 4);
    const uint32_t kRowOff = (uint32_t)(((((lane >> 4) & 1) * 8 + (lane & 7)) * AK_LD
                                         + ((lane >> 3) & 1) * 4) * 4);
    const uint32_t pRowOff = (uint32_t)(((warp * 16 + (lane & 15)) * AP_LD + (lane >> 4) * 4) * 4);
    const uint32_t qBase = smem_u32(Qs) + qRowOff;
    const uint32_t pBase = smem_u32(Ps) + pRowOff;

    auto load_kv = [&](int kt) {
        const int b = kt & 1;
        const uint32_t kb = kvb + (uint32_t)(b * KVBUF) * 4;
        const uint32_t vb = kb + (uint32_t)(KCH * AK_LD) * 4;
        const int kr0 = kt * KCH;
#pragma unroll
        for (int t = 0; t < 4; t++) {
            int fid = tid + 256 * t;
            int r = fid >> 5, c4 = (fid & 31) * 4;
            const uint32_t* s = qkv + ((size_t)(kr0 + r) * BATCH + bb) * QKV_N + hoff + HDIM + c4;
            cp16(kb + (uint32_t)(r * AK_LD + c4) * 4, s);
            cp16(vb + (uint32_t)(r * AV_LD + c4) * 4, s + HDIM);
        }
        asm volatile("cp.async.commit_group;" ::: "memory");
    };

    {
        uint32_t qsb = smem_u32(Qs);
#pragma unroll
        for (int t = 0; t < 16; t++) {
            int fid = tid + 256 * t;
            int r = fid >> 5, c4 = (fid & 31) * 4;
            const uint32_t* s = qkv + ((size_t)(q0 + r) * BATCH + bb) * QKV_N + hoff + c4;
            cp16(qsb + (uint32_t)(r * AQ_LD + c4) * 4, s);
        }
    }
    load_kv(0);

    float o[16][4];
#pragma unroll
    for (int j = 0; j < 16; j++)
#pragma unroll
        for (int q = 0; q < 4; q++) o[j][q] = 0.f;
    float m0r = -1e30f, m1r = -1e30f, l0r = 0.f, l1r = 0.f;
    const float scale = 0.08838834764831845f;    // 1/sqrt(128)

    const int nkt = 4 * qt + 4;
    for (int kt = 0; kt < nkt; kt++) {
        asm volatile("cp.async.wait_group 0;" ::: "memory");
        __syncthreads();
        if (kt + 1 < nkt) load_kv(kt + 1);

        const int b = kt & 1;
        const uint32_t kBase = kvb + (uint32_t)(b * KVBUF) * 4 + kRowOff;
        const uint32_t* Vb = KV + b * KVBUF + KCH * AK_LD;
        const int kr0 = kt * KCH;
        const int rowg = q0 + warp * 16 + g;
        const bool active = (kr0 <= q0 + warp * 16 + 15);

        if (active) {
            float s[4][4];
#pragma unroll
            for (int j = 0; j < 4; j++)
#pragma unroll
                for (int q = 0; q < 4; q++) s[j][q] = 0.f;
#pragma unroll
            for (int kk = 0; kk < 16; kk++) {
                uint32_t a[4], bv0[4], bv1[4];
                ldsm4(a, qBase + kk * 32);
                ldsm4(bv0, kBase + kk * 32);                          // j tiles 0,1
                ldsm4(bv1, kBase + (uint32_t)(16 * AK_LD) * 4 + kk * 32); // j tiles 2,3
                mma8(s[0], a, bv0[0], bv0[1]);
                mma8(s[1], a, bv0[2], bv0[3]);
                mma8(s[2], a, bv1[0], bv1[1]);
                mma8(s[3], a, bv1[2], bv1[3]);
            }
#pragma unroll
            for (int j = 0; j < 4; j++) {
                int cb = kr0 + j * 8 + 2 * tg;
                s[j][0] = (cb     > rowg)     ? -10000.f : s[j][0] * scale;
                s[j][1] = (cb + 1 > rowg)     ? -10000.f : s[j][1] * scale;
                s[j][2] = (cb     > rowg + 8) ? -10000.f : s[j][2] * scale;
                s[j][3] = (cb + 1 > rowg + 8) ? -10000.f : s[j][3] * scale;
            }
            {
                float ml = -1e30f;
#pragma unroll
                for (int j = 0; j < 4; j++) ml = fmaxf(ml, fmaxf(s[j][0], s[j][1]));
                ml = fmaxf(ml, __shfl_xor_sync(0xffffffffu, ml, 1));
                ml = fmaxf(ml, __shfl_xor_sync(0xffffffffu, ml, 2));
                float mn = fmaxf(m0r, ml);
                float corr = __expf(m0r - mn);
                float ps = 0.f;
#pragma unroll
                for (int j = 0; j < 4; j++) {
                    s[j][0] = __expf(s[j][0] - mn);
                    s[j][1] = __expf(s[j][1] - mn);
                    ps += s[j][0] + s[j][1];
                }
                ps += __shfl_xor_sync(0xffffffffu, ps, 1);
                ps += __shfl_xor_sync(0xffffffffu, ps, 2);
                l0r = l0r * corr + ps; m0r = mn;
#pragma unroll
                for (int j = 0; j < 16; j++) { o[j][0] *= corr; o[j][1] *= corr; }
            }
            {
                float ml = -1e30f;
#pragma unroll
                for (int j = 0; j < 4; j++) ml = fmaxf(ml, fmaxf(s[j][2], s[j][3]));
                ml = fmaxf(ml, __shfl_xor_sync(0xffffffffu, ml, 1));
                ml = fmaxf(ml, __shfl_xor_sync(0xffffffffu, ml, 2));
                float mn = fmaxf(m1r, ml);
                float corr = __expf(m1r - mn);
                float ps = 0.f;
#pragma unroll
                for (int j = 0; j < 4; j++) {
                    s[j][2] = __expf(s[j][2] - mn);
                    s[j][3] = __expf(s[j][3] - mn);
                    ps += s[j][2] + s[j][3];
                }
                ps += __shfl_xor_sync(0xffffffffu, ps, 1);
                ps += __shfl_xor_sync(0xffffffffu, ps, 2);
                l1r = l1r * corr + ps; m1r = mn;
#pragma unroll
                for (int j = 0; j < 16; j++) { o[j][2] *= corr; o[j][3] *= corr; }
            }
#pragma unroll
            for (int j = 0; j < 4; j++) {
                uint32_t* p0 = Ps + (warp * 16 + g) * AP_LD + j * 8 + 2 * tg;
                p0[0] = f2tf(s[j][0]); p0[1] = f2tf(s[j][1]);
                uint32_t* p1 = p0 + 8 * AP_LD;
                p1[0] = f2tf(s[j][2]); p1[1] = f2tf(s[j][3]);
            }
        }
        __syncwarp();
        if (active) {
#pragma unroll
            for (int kk = 0; kk < 4; kk++) {
                uint32_t a[4];
                ldsm4(a, pBase + kk * 32);
#pragma unroll
                for (int j = 0; j < 16; j++) {
                    const uint32_t* vp = Vb + (kk * 8 + tg) * AV_LD + j * 8 + g;
                    mma8(o[j], a, vp[0], vp[4 * AV_LD]);
                }
            }
        }
    }

    const float i0 = 1.f / l0r, i1 = 1.f / l1r;
    const int r0g = q0 + warp * 16 + g;
#pragma unroll
    for (int j = 0; j < 16; j++) {
        int col = head * HDIM + j * 8 + 2 * tg;
        uint2 v0 = { f2tf(o[j][0] * i0), f2tf(o[j][1] * i0) };
        uint2 v1 = { f2tf(o[j][2] * i1), f2tf(o[j][3] * i1) };
        *(uint2*)(ctx + ((size_t)r0g * BATCH + bb) * HID + col) = v0;
        *(uint2*)(ctx + ((size_t)(r0g + 8) * BATCH + bb) * HID + col) = v1;
    }
}

// ---------------------------------------------------------------------------
extern "C" void kernel_launch(void* const* d_in, const int* in_sizes, int n_in,
                              void* d_out, int out_size)
{
    const float* hs      = (const float*)d_in[0];
    const float* w_qkv   = (const float*)d_in[2];
    const float* b_qkv   = (const float*)d_in[3];
    const float* w_dense = (const float*)d_in[4];
    const float* b_dense = (const float*)d_in[5];
    float* out = (float*)d_out;

    uint32_t *hs_t, *wqkv_t, *wd_t, *ctx_t, *qkv_buf;
    cudaGetSymbolAddress((void**)&hs_t, g_hs_t);
    cudaGetSymbolAddress((void**)&wqkv_t, g_wqkv_t);
    cudaGetSymbolAddress((void**)&wd_t, g_wd_t);
    cudaGetSymbolAddress((void**)&qkv_buf, g_qkv);
    cudaGetSymbolAddress((void**)&ctx_t, g_ctx_t);

    cudaFuncSetAttribute(gemm_tf32, cudaFuncAttributeMaxDynamicSharedMemorySize, GEMM_SMEM_BYTES);
    cudaFuncSetAttribute(attn_tf32, cudaFuncAttributeMaxDynamicSharedMemorySize, ATT_BYTES);

    // 0) pre-round GEMM operands to tf32 (rna)
    {
        int n4;
        n4 = ROWS * HID / 4;
        cvt_tf32_kernel<<<(n4 + 255) / 256, 256>>>((const float4*)hs, (uint4*)hs_t, n4);
        n4 = QKV_N * HID / 4;
        cvt_tf32_kernel<<<(n4 + 255) / 256, 256>>>((const float4*)w_qkv, (uint4*)wqkv_t, n4);
        n4 = HID * HID / 4;
        cvt_tf32_kernel<<<(n4 + 255) / 256, 256>>>((const float4*)w_dense, (uint4*)wd_t, n4);
    }

    // 1) QKV projection: qkv(tf32 bits) = hs @ w_qkv^T + b_qkv
    gemm_tf32<<<dim3(QKV_N / GBN, ROWS / GBM), GTHREADS, GEMM_SMEM_BYTES>>>(
        hs_t, wqkv_t, b_qkv, qkv_buf, ROWS, QKV_N, HID, 1, 1);

    // 2) causal flash attention -> ctx (tf32 bits)
    attn_tf32<<<dim3(S_LEN / 128, NHEAD, BATCH), 256, ATT_BYTES>>>(qkv_buf, ctx_t);

    // 3) dense projection: out(fp32) = ctx @ w_dense^T (skip_bias_add)
    gemm_tf32<<<dim3(HID / GBN, ROWS / GBM), GTHREADS, GEMM_SMEM_BYTES>>>(
        ctx_t, wd_t, nullptr, (uint32_t*)out, ROWS, HID, HID, 0, 0);

    // 4) b_dense returned separately -> tail of d_out
    if (out_size >= (int)((size_t)ROWS * HID + HID)) {
        cudaMemcpyAsync(out + (size_t)ROWS * HID, b_dense,
                        HID * sizeof(float), cudaMemcpyDeviceToDevice);
    }
}

// round 11
// speedup vs baseline: 1.1813x; 1.0041x over previous
#include <cuda_runtime.h>
#include <math.h>
#include <stdint.h>

#define S_LEN 2048
#define BATCH 2
#define HID 2048
#define NHEAD 16
#define HDIM 128
#define QKV_N 6144
#define ROWS 4096

// ---------------- scratch (device globals; allocation forbidden) -----------
__device__ uint32_t g_hs_t[(size_t)ROWS * HID];      // tf32 bits of hidden_states
__device__ uint32_t g_wqkv_t[(size_t)QKV_N * HID];   // tf32 bits of w_qkv
__device__ uint32_t g_wd_t[(size_t)HID * HID];       // tf32 bits of w_dense
__device__ uint32_t g_qkv[(size_t)ROWS * QKV_N];     // tf32 bits of qkv
__device__ uint32_t g_vt[(size_t)BATCH * NHEAD * HDIM * S_LEN];  // V transposed
__device__ uint32_t g_ctx_t[(size_t)ROWS * HID];     // tf32 bits of ctx

// ---------------- helpers --------------------------------------------------
__device__ __forceinline__ uint32_t f2tf(float x) {
    uint32_t r; asm("cvt.rna.tf32.f32 %0, %1;" : "=r"(r) : "f"(x)); return r;
}
__device__ __forceinline__ void mma8(float* c, const uint32_t* a, uint32_t b0, uint32_t b1) {
    asm volatile("mma.sync.aligned.m16n8k8.row.col.f32.tf32.tf32.f32 "
        "{%0,%1,%2,%3},{%4,%5,%6,%7},{%8,%9},{%0,%1,%2,%3};"
        : "+f"(c[0]), "+f"(c[1]), "+f"(c[2]), "+f"(c[3])
        : "r"(a[0]), "r"(a[1]), "r"(a[2]), "r"(a[3]), "r"(b0), "r"(b1));
}
__device__ __forceinline__ void ldsm4(uint32_t* r, uint32_t addr) {
    asm volatile("ldmatrix.sync.aligned.m8n8.x4.shared.b16 {%0,%1,%2,%3}, [%4];"
        : "=r"(r[0]), "=r"(r[1]), "=r"(r[2]), "=r"(r[3]) : "r"(addr));
}
__device__ __forceinline__ void cp16(uint32_t saddr, const void* gptr) {
    asm volatile("cp.async.cg.shared.global [%0], [%1], 16;" :: "r"(saddr), "l"(gptr));
}
__device__ __forceinline__ uint32_t smem_u32(const void* p) {
    uint32_t a;
    asm("{ .reg .u64 t; cvta.to.shared.u64 t, %1; cvt.u32.u64 %0, t; }" : "=r"(a) : "l"(p));
    return a;
}

#define MBAR_INIT(addr, cnt) \
    asm volatile("mbarrier.init.shared.b64 [%0], %1;" :: "r"(addr), "r"(cnt) : "memory")
#define MBAR_ARRIVE(addr) \
    asm volatile("mbarrier.arrive.shared.b64 _, [%0];" :: "r"(addr) : "memory")
#define MBAR_ARRIVE_CPASYNC(addr) \
    asm volatile("cp.async.mbarrier.arrive.noinc.shared.b64 [%0];" :: "r"(addr) : "memory")
#define MBAR_WAIT(addr, par) do {                                               \
    uint32_t _done;                                                             \
    asm volatile("{ .reg .pred p; mbarrier.try_wait.parity.acquire.cta.shared::cta.b64 p, [%1], %2; selp.b32 %0,1,0,p; }" \
        : "=r"(_done) : "r"(addr), "r"(par) : "memory");                        \
    while (!_done) {                                                            \
        asm volatile("{ .reg .pred p; mbarrier.try_wait.parity.acquire.cta.shared::cta.b64 p, [%1], %2, 0x989680; selp.b32 %0,1,0,p; }" \
            : "=r"(_done) : "r"(addr), "r"(par) : "memory");                    \
    }                                                                           \
} while (0)

// ---------------- fp32 -> tf32 conversion kernel ---------------------------
__global__ void cvt_tf32_kernel(const float4* __restrict__ in, uint4* __restrict__ out, int n4) {
    int i = blockIdx.x * blockDim.x + threadIdx.x;
    if (i < n4) {
        float4 v = in[i];
        uint4 o;
        o.x = f2tf(v.x); o.y = f2tf(v.y); o.z = f2tf(v.z); o.w = f2tf(v.w);
        out[i] = o;
    }
}

// ---------------- V transpose: qkv V columns -> vt[b][h][hd][S] -------------
// V lives at head*384 + 2*HDIM + hd within a qkv row.
__global__ __launch_bounds__(256, 4)
void transpose_v(const uint32_t* __restrict__ qkv, uint32_t* __restrict__ vt)
{
    __shared__ uint32_t tile[32][33];
    const int st = blockIdx.x;            // 64 s-tiles of 32
    const int ht = blockIdx.y;            // 4 hd-tiles of 32
    const int bh = blockIdx.z;            // b*16 + head
    const int head = bh & 15, bb = bh >> 4;
    const int tx = threadIdx.x & 31, ty = threadIdx.x >> 5;

#pragma unroll
    for (int rr = 0; rr < 4; rr++) {
        int s = st * 32 + ty + rr * 8;
        int hd = ht * 32 + tx;
        tile[ty + rr * 8][tx] =
            qkv[((size_t)s * BATCH + bb) * QKV_N + head * 384 + 2 * HDIM + hd];
    }
    __syncthreads();
#pragma unroll
    for (int rr = 0; rr < 4; rr++) {
        int hd = ht * 32 + ty + rr * 8;
        int s = st * 32 + tx;
        vt[((size_t)(bb * NHEAD + head) * HDIM + hd) * S_LEN + s] = tile[tx][ty + rr * 8];
    }
}

// ---------------- tf32 GEMM: C[m,n] = A[m,:] . B[n,:] (+bias) --------------
// CTA 128x128, BK=32, 128 threads = 2x2 warps with 64x64 tiles. 3-stage
// mbarrier ring. Fragment loads via ldmatrix.x4.
#define GBM 128
#define GBN 128
#define GBK 32
#define SLD 36
#define TSZ (128 * SLD)
#define GEMM_SMEM_BYTES (3 * 2 * TSZ * 4)       // 110592
#define GTHREADS 128

__global__ __launch_bounds__(GTHREADS, 2)
void gemm_tf32(const uint32_t* __restrict__ A, const uint32_t* __restrict__ B,
               const float* __restrict__ bias, uint32_t* __restrict__ C,
               int M, int N, int K, int add_bias, int out_tf32)
{
    extern __shared__ uint32_t sm[];
    __shared__ uint64_t bars[6];                 // full[0..2], empty[0..2]

    const int tid = threadIdx.x;
    const int lane = tid & 31, warp = tid >> 5;
    const int g = lane >> 2, tg = lane & 3;
    const int wm = warp >> 1, wn = warp & 1;     // 2 x 2 warps
    const int m0 = blockIdx.y * GBM, n0 = blockIdx.x * GBN;
    const uint32_t smb = smem_u32(sm);
    const uint32_t barb = smem_u32(bars);
#define FULLB(s)  (barb + 8u * (uint32_t)(s))
#define EMPTYB(s) (barb + 24u + 8u * (uint32_t)(s))

    if (tid == 0) {
#pragma unroll
        for (int s = 0; s < 3; s++) {
            MBAR_INIT(FULLB(s), GTHREADS);
            MBAR_INIT(EMPTYB(s), GTHREADS);
        }
    }
    __syncthreads();

    const uint32_t aRowOff = (uint32_t)(((wm * 64 + (lane & 15)) * SLD + (lane >> 4) * 4) * 4);
    const uint32_t bRowOff = (uint32_t)(((wn * 64 + ((lane >> 4) & 1) * 8 + (lane & 7)) * SLD
                                         + ((lane >> 3) & 1) * 4) * 4);

    float c[4][8][4];                            // 64x64 warp tile
#pragma unroll
    for (int i = 0; i < 4; i++)
#pragma unroll
        for (int j = 0; j < 8; j++)
#pragma unroll
            for (int q = 0; q < 4; q++) c[i][j][q] = 0.f;

    auto load_stage = [&](int it) {
        const int buf = it % 3;
        uint32_t ab = smb + (uint32_t)(buf * 2 * TSZ) * 4;
        uint32_t bb = ab + (uint32_t)TSZ * 4;
        const int k0 = it * GBK;
#pragma unroll
        for (int t = 0; t < 8; t++) {
            int fid = tid + GTHREADS * t;
            int r = fid >> 3, c4 = (fid & 7) * 4;
            cp16(ab + (uint32_t)(r * SLD + c4) * 4, A + (size_t)(m0 + r) * K + k0 + c4);
            cp16(bb + (uint32_t)(r * SLD + c4) * 4, B + (size_t)(n0 + r) * K + k0 + c4);
        }
        MBAR_ARRIVE_CPASYNC(FULLB(buf));
    };

    const int NI = K / GBK;
    load_stage(0);
    load_stage(1);

    for (int it = 0; it < NI; it++) {
        const int nx = it + 2;
        if (nx < NI) {
            const int qn = nx % 3, rn = nx / 3;
            if (rn >= 1) MBAR_WAIT(EMPTYB(qn), (uint32_t)((rn - 1) & 1));
            load_stage(nx);
        }
        const int q = it % 3;
        MBAR_WAIT(FULLB(q), (uint32_t)((it / 3) & 1));

        const uint32_t aBase = smb + (uint32_t)(q * 2 * TSZ) * 4 + aRowOff;
        const uint32_t bBase = smb + (uint32_t)(q * 2 * TSZ + TSZ) * 4 + bRowOff;
#pragma unroll
        for (int kk = 0; kk < 4; kk++) {
            uint32_t a[4][4], bv[4][4];
#pragma unroll
            for (int i = 0; i < 4; i++)
                ldsm4(a[i], aBase + (uint32_t)(i * 16 * SLD) * 4 + kk * 32);
#pragma unroll
            for (int jp = 0; jp < 4; jp++)
                ldsm4(bv[jp], bBase + (uint32_t)(jp * 16 * SLD) * 4 + kk * 32);
#pragma unroll
            for (int jp = 0; jp < 4; jp++)
#pragma unroll
                for (int i = 0; i < 4; i++) {
                    mma8(c[i][2 * jp],     a[i], bv[jp][0], bv[jp][1]);
                    mma8(c[i][2 * jp + 1], a[i], bv[jp][2], bv[jp][3]);
                }
        }
        MBAR_ARRIVE(EMPTYB(q));
    }

#pragma unroll
    for (int i = 0; i < 4; i++) {
        int row = m0 + wm * 64 + i * 16 + g;
#pragma unroll
        for (int j = 0; j < 8; j++) {
            int col = n0 + wn * 64 + j * 8 + 2 * tg;
            float b0 = add_bias ? bias[col] : 0.f;
            float b1 = add_bias ? bias[col + 1] : 0.f;
            float v00 = c[i][j][0] + b0, v01 = c[i][j][1] + b1;
            float v10 = c[i][j][2] + b0, v11 = c[i][j][3] + b1;
            uint2 r0, r1;
            if (out_tf32) {
                r0.x = f2tf(v00); r0.y = f2tf(v01);
                r1.x = f2tf(v10); r1.y = f2tf(v11);
            } else {
                r0.x = __float_as_uint(v00); r0.y = __float_as_uint(v01);
                r1.x = __float_as_uint(v10); r1.y = __float_as_uint(v11);
            }
            *(uint2*)(C + (size_t)row * N + col) = r0;
            *(uint2*)(C + (size_t)(row + 8) * N + col) = r1;
        }
    }
#undef FULLB
#undef EMPTYB
}

// ---------------- tf32 flash attention --------------------------------------
// Q tile 128 (warp owns 16 rows; fragments hoisted to registers). K chunk
// [32][AK_LD] + V^T chunk [128][VT_LD] double-buffered. All MMA operands via
// ldmatrix.
#define AQ_LD 132
#define AK_LD 132
#define VT_LD 36
#define AP_LD 36
#define KCH 32
#define KVBUF (KCH * AK_LD + HDIM * VT_LD)      // 8832 words
#define ATT_WORDS (128 * AQ_LD + 2 * KVBUF + 128 * AP_LD)
#define ATT_BYTES (ATT_WORDS * 4)               // 156672

__global__ __launch_bounds__(256, 1)
void attn_tf32(const uint32_t* __restrict__ qkv, const uint32_t* __restrict__ vt,
               uint32_t* __restrict__ ctx)
{
    extern __shared__ uint32_t sm[];
    uint32_t* Qs = sm;
    uint32_t* KV = Qs + 128 * AQ_LD;
    uint32_t* Ps = KV + 2 * KVBUF;
    const uint32_t kvb = smem_u32(KV);

    const int tid = threadIdx.x, lane = tid & 31, warp = tid >> 5;
    const int g = lane >> 2, tg = lane & 3;
    const int qt = gridDim.x - 1 - blockIdx.x;   // heavy tiles first
    const int head = blockIdx.y, bb = blockIdx.z;
    const int q0 = qt * 128;
    const size_t hoff = (size_t)head * (3 * HDIM);
    const uint32_t* vtp = vt + (size_t)(bb * NHEAD + head) * HDIM * S_LEN;

    // ldmatrix row offsets
    const uint32_t qRowOff = (uint32_t)(((warp * 16 + (lane & 15)) * AQ_LD + (lane >> 4) * 4) * 4);
    const uint32_t kRowOff = (uint32_t)(((((lane >> 4) & 1) * 8 + (lane & 7)) * AK_LD
                                         + ((lane >> 3) & 1) * 4) * 4);
    const uint32_t vRowOff = (uint32_t)(((((lane >> 4) & 1) * 8 + (lane & 7)) * VT_LD
                                         + ((lane >> 3) & 1) * 4) * 4);
    const uint32_t pRowOff = (uint32_t)(((warp * 16 + (lane & 15)) * AP_LD + (lane >> 4) * 4) * 4);
    const uint32_t pBase = smem_u32(Ps) + pRowOff;

    auto load_kv = [&](int kt) {
        const int b = kt & 1;
        const uint32_t kb = kvb + (uint32_t)(b * KVBUF) * 4;
        const uint32_t vb = kb + (uint32_t)(KCH * AK_LD) * 4;
        const int kr0 = kt * KCH;
#pragma unroll
        for (int t = 0; t < 4; t++) {            // K: 32 rows x 32 words
            int fid = tid + 256 * t;
            int r = fid >> 5, c4 = (fid & 31) * 4;
            const uint32_t* s = qkv + ((size_t)(kr0 + r) * BATCH + bb) * QKV_N + hoff + HDIM + c4;
            cp16(kb + (uint32_t)(r * AK_LD + c4) * 4, s);
        }
#pragma unroll
        for (int t = 0; t < 4; t++) {            // V^T: 128 rows x 32 words
            int fid = tid + 256 * t;
            int r = fid >> 3, c4 = (fid & 7) * 4;
            cp16(vb + (uint32_t)(r * VT_LD + c4) * 4, vtp + (size_t)r * S_LEN + kr0 + c4);
        }
        asm volatile("cp.async.commit_group;" ::: "memory");
    };

    // prologue: Q tile + KV chunk 0
    {
        uint32_t qsb = smem_u32(Qs);
#pragma unroll
        for (int t = 0; t < 16; t++) {
            int fid = tid + 256 * t;
            int r = fid >> 5, c4 = (fid & 31) * 4;
            const uint32_t* s = qkv + ((size_t)(q0 + r) * BATCH + bb) * QKV_N + hoff + c4;
            cp16(qsb + (uint32_t)(r * AQ_LD + c4) * 4, s);
        }
    }
    load_kv(0);
    asm volatile("cp.async.wait_group 0;" ::: "memory");
    __syncthreads();

    // hoist Q fragments (loop-invariant)
    uint32_t qf[16][4];
    {
        const uint32_t qBase = smem_u32(Qs) + qRowOff;
#pragma unroll
        for (int kk = 0; kk < 16; kk++) ldsm4(qf[kk], qBase + kk * 32);
    }

    const int nkt = 4 * qt + 4;
    if (nkt > 1) load_kv(1);

    float o[16][4];
#pragma unroll
    for (int j = 0; j < 16; j++)
#pragma unroll
        for (int q = 0; q < 4; q++) o[j][q] = 0.f;
    float m0r = -1e30f, m1r = -1e30f, l0r = 0.f, l1r = 0.f;
    const float scale = 0.08838834764831845f;    // 1/sqrt(128)

    for (int kt = 0; kt < nkt; kt++) {
        if (kt > 0) {
            asm volatile("cp.async.wait_group 0;" ::: "memory");
            __syncthreads();
            if (kt + 1 < nkt) load_kv(kt + 1);
        }
        const int b = kt & 1;
        const uint32_t kBase = kvb + (uint32_t)(b * KVBUF) * 4 + kRowOff;
        const uint32_t vBase = kvb + (uint32_t)(b * KVBUF + KCH * AK_LD) * 4 + vRowOff;
        const int kr0 = kt * KCH;
        const int rowg = q0 + warp * 16 + g;
        const bool active = (kr0 <= q0 + warp * 16 + 15);

        if (active) {
            float s[4][4];
#pragma unroll
            for (int j = 0; j < 4; j++)
#pragma unroll
                for (int q = 0; q < 4; q++) s[j][q] = 0.f;
#pragma unroll
            for (int kk = 0; kk < 16; kk++) {
                uint32_t bv0[4], bv1[4];
                ldsm4(bv0, kBase + kk * 32);                              // j tiles 0,1
                ldsm4(bv1, kBase + (uint32_t)(16 * AK_LD) * 4 + kk * 32); // j tiles 2,3
                mma8(s[0], qf[kk], bv0[0], bv0[1]);
                mma8(s[1], qf[kk], bv0[2], bv0[3]);
                mma8(s[2], qf[kk], bv1[0], bv1[1]);
                mma8(s[3], qf[kk], bv1[2], bv1[3]);
            }
#pragma unroll
            for (int j = 0; j < 4; j++) {
                int cb = kr0 + j * 8 + 2 * tg;
                s[j][0] = (cb     > rowg)     ? -10000.f : s[j][0] * scale;
                s[j][1] = (cb + 1 > rowg)     ? -10000.f : s[j][1] * scale;
                s[j][2] = (cb     > rowg + 8) ? -10000.f : s[j][2] * scale;
                s[j][3] = (cb + 1 > rowg + 8) ? -10000.f : s[j][3] * scale;
            }
            {
                float ml = -1e30f;
#pragma unroll
                for (int j = 0; j < 4; j++) ml = fmaxf(ml, fmaxf(s[j][0], s[j][1]));
                ml = fmaxf(ml, __shfl_xor_sync(0xffffffffu, ml, 1));
                ml = fmaxf(ml, __shfl_xor_sync(0xffffffffu, ml, 2));
                float mn = fmaxf(m0r, ml);
                float corr = __expf(m0r - mn);
                float ps = 0.f;
#pragma unroll
                for (int j = 0; j < 4; j++) {
                    s[j][0] = __expf(s[j][0] - mn);
                    s[j][1] = __expf(s[j][1] - mn);
                    ps += s[j][0] + s[j][1];
                }
                ps += __shfl_xor_sync(0xffffffffu, ps, 1);
                ps += __shfl_xor_sync(0xffffffffu, ps, 2);
                l0r = l0r * corr + ps; m0r = mn;
#pragma unroll
                for (int j = 0; j < 16; j++) { o[j][0] *= corr; o[j][1] *= corr; }
            }
            {
                float ml = -1e30f;
#pragma unroll
                for (int j = 0; j < 4; j++) ml = fmaxf(ml, fmaxf(s[j][2], s[j][3]));
                ml = fmaxf(ml, __shfl_xor_sync(0xffffffffu, ml, 1));
                ml = fmaxf(ml, __shfl_xor_sync(0xffffffffu, ml, 2));
                float mn = fmaxf(m1r, ml);
                float corr = __expf(m1r - mn);
                float ps = 0.f;
#pragma unroll
                for (int j = 0; j < 4; j++) {
                    s[j][2] = __expf(s[j][2] - mn);
                    s[j][3] = __expf(s[j][3] - mn);
                    ps += s[j][2] + s[j][3];
                }
                ps += __shfl_xor_sync(0xffffffffu, ps, 1);
                ps += __shfl_xor_sync(0xffffffffu, ps, 2);
                l1r = l1r * corr + ps; m1r = mn;
#pragma unroll
                for (int j = 0; j < 16; j++) { o[j][2] *= corr; o[j][3] *= corr; }
            }
#pragma unroll
            for (int j = 0; j < 4; j++) {
                uint32_t* p0 = Ps + (warp * 16 + g) * AP_LD + j * 8 + 2 * tg;
                p0[0] = f2tf(s[j][0]); p0[1] = f2tf(s[j][1]);
                uint32_t* p1 = p0 + 8 * AP_LD;
                p1[0] = f2tf(s[j][2]); p1[1] = f2tf(s[j][3]);
            }
        }
        __syncwarp();
        if (active) {
            // O += P @ V  via ldmatrix on V^T (n-major, same pattern as K)
#pragma unroll
            for (int kk = 0; kk < 4; kk++) {
                uint32_t a[4];
                ldsm4(a, pBase + kk * 32);
#pragma unroll
                for (int jp = 0; jp < 8; jp++) {
                    uint32_t v[4];
                    ldsm4(v, vBase + (uint32_t)(jp * 16 * VT_LD) * 4 + kk * 32);
                    mma8(o[2 * jp],     a, v[0], v[1]);
                    mma8(o[2 * jp + 1], a, v[2], v[3]);
                }
            }
        }
    }

    const float i0 = 1.f / l0r, i1 = 1.f / l1r;
    const int r0g = q0 + warp * 16 + g;
#pragma unroll
    for (int j = 0; j < 16; j++) {
        int col = head * HDIM + j * 8 + 2 * tg;
        uint2 v0 = { f2tf(o[j][0] * i0), f2tf(o[j][1] * i0) };
        uint2 v1 = { f2tf(o[j][2] * i1), f2tf(o[j][3] * i1) };
        *(uint2*)(ctx + ((size_t)r0g * BATCH + bb) * HID + col) = v0;
        *(uint2*)(ctx + ((size_t)(r0g + 8) * BATCH + bb) * HID + col) = v1;
    }
}

// ---------------------------------------------------------------------------
extern "C" void kernel_launch(void* const* d_in, const int* in_sizes, int n_in,
                              void* d_out, int out_size)
{
    const float* hs      = (const float*)d_in[0];
    const float* w_qkv   = (const float*)d_in[2];
    const float* b_qkv   = (const float*)d_in[3];
    const float* w_dense = (const float*)d_in[4];
    const float* b_dense = (const float*)d_in[5];
    float* out = (float*)d_out;

    uint32_t *hs_t, *wqkv_t, *wd_t, *ctx_t, *qkv_buf, *vt_buf;
    cudaGetSymbolAddress((void**)&hs_t, g_hs_t);
    cudaGetSymbolAddress((void**)&wqkv_t, g_wqkv_t);
    cudaGetSymbolAddress((void**)&wd_t, g_wd_t);
    cudaGetSymbolAddress((void**)&qkv_buf, g_qkv);
    cudaGetSymbolAddress((void**)&vt_buf, g_vt);
    cudaGetSymbolAddress((void**)&ctx_t, g_ctx_t);

    cudaFuncSetAttribute(gemm_tf32, cudaFuncAttributeMaxDynamicSharedMemorySize, GEMM_SMEM_BYTES);
    cudaFuncSetAttribute(attn_tf32, cudaFuncAttributeMaxDynamicSharedMemorySize, ATT_BYTES);

    // 0) pre-round GEMM operands to tf32 (rna)
    {
        int n4;
        n4 = ROWS * HID / 4;
        cvt_tf32_kernel<<<(n4 + 255) / 256, 256>>>((const float4*)hs, (uint4*)hs_t, n4);
        n4 = QKV_N * HID / 4;
        cvt_tf32_kernel<<<(n4 + 255) / 256, 256>>>((const float4*)w_qkv, (uint4*)wqkv_t, n4);
        n4 = HID * HID / 4;
        cvt_tf32_kernel<<<(n4 + 255) / 256, 256>>>((const float4*)w_dense, (uint4*)wd_t, n4);
    }

    // 1) QKV projection: qkv(tf32 bits) = hs @ w_qkv^T + b_qkv
    gemm_tf32<<<dim3(QKV_N / GBN, ROWS / GBM), GTHREADS, GEMM_SMEM_BYTES>>>(
        hs_t, wqkv_t, b_qkv, qkv_buf, ROWS, QKV_N, HID, 1, 1);

    // 1b) transpose V -> vt[b][h][hd][S]
    transpose_v<<<dim3(S_LEN / 32, HDIM / 32, BATCH * NHEAD), 256>>>(qkv_buf, vt_buf);

    // 2) causal flash attention -> ctx (tf32 bits)
    attn_tf32<<<dim3(S_LEN / 128, NHEAD, BATCH), 256, ATT_BYTES>>>(qkv_buf, vt_buf, ctx_t);

    // 3) dense projection: out(fp32) = ctx @ w_dense^T (skip_bias_add)
    gemm_tf32<<<dim3(HID / GBN, ROWS / GBM), GTHREADS, GEMM_SMEM_BYTES>>>(
        ctx_t, wd_t, nullptr, (uint32_t*)out, ROWS, HID, HID, 0, 0);

    // 4) b_dense returned separately -> tail of d_out
    if (out_size >= (int)((size_t)ROWS * HID + HID)) {
        cudaMemcpyAsync(out + (size_t)ROWS * HID, b_dense,
                        HID * sizeof(float), cudaMemcpyDeviceToDevice);
    }
}

// round 12
// speedup vs baseline: 1.2299x; 1.0411x over previous
#include <cuda_runtime.h>
#include <math.h>
#include <stdint.h>

#define S_LEN 2048
#define BATCH 2
#define HID 2048
#define NHEAD 16
#define HDIM 128
#define QKV_N 6144
#define ROWS 4096

// ---------------- scratch (device globals; allocation forbidden) -----------
__device__ uint32_t g_hs_t[(size_t)ROWS * HID];      // tf32 bits of hidden_states
__device__ uint32_t g_wqkv_t[(size_t)QKV_N * HID];   // tf32 bits of w_qkv
__device__ uint32_t g_wd_t[(size_t)HID * HID];       // tf32 bits of w_dense
__device__ uint32_t g_qkv[(size_t)ROWS * QKV_N];     // tf32 bits of qkv
__device__ uint32_t g_vt[(size_t)BATCH * NHEAD * HDIM * S_LEN];  // V transposed
__device__ uint32_t g_ctx_t[(size_t)ROWS * HID];     // tf32 bits of ctx

// ---------------- helpers --------------------------------------------------
__device__ __forceinline__ uint32_t f2tf(float x) {
    uint32_t r; asm("cvt.rna.tf32.f32 %0, %1;" : "=r"(r) : "f"(x)); return r;
}
__device__ __forceinline__ void mma8(float* c, const uint32_t* a, uint32_t b0, uint32_t b1) {
    asm volatile("mma.sync.aligned.m16n8k8.row.col.f32.tf32.tf32.f32 "
        "{%0,%1,%2,%3},{%4,%5,%6,%7},{%8,%9},{%0,%1,%2,%3};"
        : "+f"(c[0]), "+f"(c[1]), "+f"(c[2]), "+f"(c[3])
        : "r"(a[0]), "r"(a[1]), "r"(a[2]), "r"(a[3]), "r"(b0), "r"(b1));
}
__device__ __forceinline__ void ldsm4(uint32_t* r, uint32_t addr) {
    asm volatile("ldmatrix.sync.aligned.m8n8.x4.shared.b16 {%0,%1,%2,%3}, [%4];"
        : "=r"(r[0]), "=r"(r[1]), "=r"(r[2]), "=r"(r[3]) : "r"(addr));
}
__device__ __forceinline__ void cp16(uint32_t saddr, const void* gptr) {
    asm volatile("cp.async.cg.shared.global [%0], [%1], 16;" :: "r"(saddr), "l"(gptr));
}
__device__ __forceinline__ uint32_t smem_u32(const void* p) {
    uint32_t a;
    asm("{ .reg .u64 t; cvta.to.shared.u64 t, %1; cvt.u32.u64 %0, t; }" : "=r"(a) : "l"(p));
    return a;
}

#define MBAR_INIT(addr, cnt) \
    asm volatile("mbarrier.init.shared.b64 [%0], %1;" :: "r"(addr), "r"(cnt) : "memory")
#define MBAR_ARRIVE(addr) \
    asm volatile("mbarrier.arrive.shared.b64 _, [%0];" :: "r"(addr) : "memory")
#define MBAR_ARRIVE_CPASYNC(addr) \
    asm volatile("cp.async.mbarrier.arrive.noinc.shared.b64 [%0];" :: "r"(addr) : "memory")
#define MBAR_WAIT(addr, par) do {                                               \
    uint32_t _done;                                                             \
    asm volatile("{ .reg .pred p; mbarrier.try_wait.parity.acquire.cta.shared::cta.b64 p, [%1], %2; selp.b32 %0,1,0,p; }" \
        : "=r"(_done) : "r"(addr), "r"(par) : "memory");                        \
    while (!_done) {                                                            \
        asm volatile("{ .reg .pred p; mbarrier.try_wait.parity.acquire.cta.shared::cta.b64 p, [%1], %2, 0x989680; selp.b32 %0,1,0,p; }" \
            : "=r"(_done) : "r"(addr), "r"(par) : "memory");                    \
    }                                                                           \
} while (0)

// ---------------- fp32 -> tf32 conversion kernel ---------------------------
__global__ void cvt_tf32_kernel(const float4* __restrict__ in, uint4* __restrict__ out, int n4) {
    int i = blockIdx.x * blockDim.x + threadIdx.x;
    if (i < n4) {
        float4 v = in[i];
        uint4 o;
        o.x = f2tf(v.x); o.y = f2tf(v.y); o.z = f2tf(v.z); o.w = f2tf(v.w);
        out[i] = o;
    }
}

// ---------------- V transpose: qkv V columns -> vt[b][h][hd][S] -------------
// V lives at head*384 + 2*HDIM + hd within a qkv row.
__global__ __launch_bounds__(256, 4)
void transpose_v(const uint32_t* __restrict__ qkv, uint32_t* __restrict__ vt)
{
    __shared__ uint32_t tile[32][33];
    const int st = blockIdx.x;            // 64 s-tiles of 32
    const int ht = blockIdx.y;            // 4 hd-tiles of 32
    const int bh = blockIdx.z;            // b*16 + head
    const int head = bh & 15, bb = bh >> 4;
    const int tx = threadIdx.x & 31, ty = threadIdx.x >> 5;

#pragma unroll
    for (int rr = 0; rr < 4; rr++) {
        int s = st * 32 + ty + rr * 8;
        int hd = ht * 32 + tx;
        tile[ty + rr * 8][tx] =
            qkv[((size_t)s * BATCH + bb) * QKV_N + head * 384 + 2 * HDIM + hd];
    }
    __syncthreads();
#pragma unroll
    for (int rr = 0; rr < 4; rr++) {
        int hd = ht * 32 + ty + rr * 8;
        int s = st * 32 + tx;
        vt[((size_t)(bb * NHEAD + head) * HDIM + hd) * S_LEN + s] = tile[tx][ty + rr * 8];
    }
}

// ---------------- tf32 GEMM: C[m,n] = A[m,:] . B[n,:] (+bias) --------------
// CTA 128x128, BK=32, 256 threads = 2x4 warps with 64x32 tiles (4 warps/SMSP
// for latency hiding; ldmatrix keeps crossbar below tensor demand). 3-stage
// mbarrier ring, 2 CTAs/SM.
#define GBM 128
#define GBN 128
#define GBK 32
#define SLD 36
#define TSZ (128 * SLD)
#define GEMM_SMEM_BYTES (3 * 2 * TSZ * 4)       // 110592
#define GTHREADS 256

__global__ __launch_bounds__(GTHREADS, 2)
void gemm_tf32(const uint32_t* __restrict__ A, const uint32_t* __restrict__ B,
               const float* __restrict__ bias, uint32_t* __restrict__ C,
               int M, int N, int K, int add_bias, int out_tf32)
{
    extern __shared__ uint32_t sm[];
    __shared__ uint64_t bars[6];                 // full[0..2], empty[0..2]

    const int tid = threadIdx.x;
    const int lane = tid & 31, warp = tid >> 5;
    const int g = lane >> 2, tg = lane & 3;
    const int wm = warp >> 2, wn = warp & 3;     // 2 x 4 warps
    const int m0 = blockIdx.y * GBM, n0 = blockIdx.x * GBN;
    const uint32_t smb = smem_u32(sm);
    const uint32_t barb = smem_u32(bars);
#define FULLB(s)  (barb + 8u * (uint32_t)(s))
#define EMPTYB(s) (barb + 24u + 8u * (uint32_t)(s))

    if (tid == 0) {
#pragma unroll
        for (int s = 0; s < 3; s++) {
            MBAR_INIT(FULLB(s), GTHREADS);
            MBAR_INIT(EMPTYB(s), GTHREADS);
        }
    }
    __syncthreads();

    // ldmatrix per-thread row offsets (bytes, stage-relative)
    const uint32_t aRowOff = (uint32_t)(((wm * 64 + (lane & 15)) * SLD + (lane >> 4) * 4) * 4);
    // B pair: 16 rows starting at wn*32 (two n8 tiles per ldsm4)
    const uint32_t bRowOff = (uint32_t)(((wn * 32 + ((lane >> 4) & 1) * 8 + (lane & 7)) * SLD
                                         + ((lane >> 3) & 1) * 4) * 4);

    float c[4][4][4];                            // 64x32 warp tile: 64 regs
#pragma unroll
    for (int i = 0; i < 4; i++)
#pragma unroll
        for (int j = 0; j < 4; j++)
#pragma unroll
            for (int q = 0; q < 4; q++) c[i][j][q] = 0.f;

    auto load_stage = [&](int it) {
        const int buf = it % 3;
        uint32_t ab = smb + (uint32_t)(buf * 2 * TSZ) * 4;
        uint32_t bb = ab + (uint32_t)TSZ * 4;
        const int k0 = it * GBK;
#pragma unroll
        for (int t = 0; t < 4; t++) {            // 128 rows x 8 16B-chunks / 256 thr
            int fid = tid + GTHREADS * t;
            int r = fid >> 3, c4 = (fid & 7) * 4;
            cp16(ab + (uint32_t)(r * SLD + c4) * 4, A + (size_t)(m0 + r) * K + k0 + c4);
            cp16(bb + (uint32_t)(r * SLD + c4) * 4, B + (size_t)(n0 + r) * K + k0 + c4);
        }
        MBAR_ARRIVE_CPASYNC(FULLB(buf));
    };

    const int NI = K / GBK;
    load_stage(0);
    load_stage(1);

    for (int it = 0; it < NI; it++) {
        const int nx = it + 2;
        if (nx < NI) {
            const int qn = nx % 3, rn = nx / 3;
            if (rn >= 1) MBAR_WAIT(EMPTYB(qn), (uint32_t)((rn - 1) & 1));
            load_stage(nx);
        }
        const int q = it % 3;
        MBAR_WAIT(FULLB(q), (uint32_t)((it / 3) & 1));

        const uint32_t aBase = smb + (uint32_t)(q * 2 * TSZ) * 4 + aRowOff;
        const uint32_t bBase = smb + (uint32_t)(q * 2 * TSZ + TSZ) * 4 + bRowOff;
#pragma unroll
        for (int kk = 0; kk < 4; kk++) {
            uint32_t a[4][4], bv[2][4];
#pragma unroll
            for (int i = 0; i < 4; i++)
                ldsm4(a[i], aBase + (uint32_t)(i * 16 * SLD) * 4 + kk * 32);
#pragma unroll
            for (int jp = 0; jp < 2; jp++)
                ldsm4(bv[jp], bBase + (uint32_t)(jp * 16 * SLD) * 4 + kk * 32);
#pragma unroll
            for (int jp = 0; jp < 2; jp++)
#pragma unroll
                for (int i = 0; i < 4; i++) {
                    mma8(c[i][2 * jp],     a[i], bv[jp][0], bv[jp][1]);
                    mma8(c[i][2 * jp + 1], a[i], bv[jp][2], bv[jp][3]);
                }
        }
        MBAR_ARRIVE(EMPTYB(q));
    }

#pragma unroll
    for (int i = 0; i < 4; i++) {
        int row = m0 + wm * 64 + i * 16 + g;
#pragma unroll
        for (int j = 0; j < 4; j++) {
            int col = n0 + wn * 32 + j * 8 + 2 * tg;
            float b0 = add_bias ? bias[col] : 0.f;
            float b1 = add_bias ? bias[col + 1] : 0.f;
            float v00 = c[i][j][0] + b0, v01 = c[i][j][1] + b1;
            float v10 = c[i][j][2] + b0, v11 = c[i][j][3] + b1;
            uint2 r0, r1;
            if (out_tf32) {
                r0.x = f2tf(v00); r0.y = f2tf(v01);
                r1.x = f2tf(v10); r1.y = f2tf(v11);
            } else {
                r0.x = __float_as_uint(v00); r0.y = __float_as_uint(v01);
                r1.x = __float_as_uint(v10); r1.y = __float_as_uint(v11);
            }
            *(uint2*)(C + (size_t)row * N + col) = r0;
            *(uint2*)(C + (size_t)(row + 8) * N + col) = r1;
        }
    }
#undef FULLB
#undef EMPTYB
}

// ---------------- tf32 flash attention --------------------------------------
// Q tile 128 (warp owns 16 rows; fragments hoisted to registers). K chunk
// [32][AK_LD] + V^T chunk [128][VT_LD] double-buffered. All MMA operands via
// ldmatrix.
#define AQ_LD 132
#define AK_LD 132
#define VT_LD 36
#define AP_LD 36
#define KCH 32
#define KVBUF (KCH * AK_LD + HDIM * VT_LD)      // 8832 words
#define ATT_WORDS (128 * AQ_LD + 2 * KVBUF + 128 * AP_LD)
#define ATT_BYTES (ATT_WORDS * 4)               // 156672

__global__ __launch_bounds__(256, 1)
void attn_tf32(const uint32_t* __restrict__ qkv, const uint32_t* __restrict__ vt,
               uint32_t* __restrict__ ctx)
{
    extern __shared__ uint32_t sm[];
    uint32_t* Qs = sm;
    uint32_t* KV = Qs + 128 * AQ_LD;
    uint32_t* Ps = KV + 2 * KVBUF;
    const uint32_t kvb = smem_u32(KV);

    const int tid = threadIdx.x, lane = tid & 31, warp = tid >> 5;
    const int g = lane >> 2, tg = lane & 3;
    const int qt = gridDim.x - 1 - blockIdx.x;   // heavy tiles first
    const int head = blockIdx.y, bb = blockIdx.z;
    const int q0 = qt * 128;
    const size_t hoff = (size_t)head * (3 * HDIM);
    const uint32_t* vtp = vt + (size_t)(bb * NHEAD + head) * HDIM * S_LEN;

    // ldmatrix row offsets
    const uint32_t qRowOff = (uint32_t)(((warp * 16 + (lane & 15)) * AQ_LD + (lane >> 4) * 4) * 4);
    const uint32_t kRowOff = (uint32_t)(((((lane >> 4) & 1) * 8 + (lane & 7)) * AK_LD
                                         + ((lane >> 3) & 1) * 4) * 4);
    const uint32_t vRowOff = (uint32_t)(((((lane >> 4) & 1) * 8 + (lane & 7)) * VT_LD
                                         + ((lane >> 3) & 1) * 4) * 4);
    const uint32_t pRowOff = (uint32_t)(((warp * 16 + (lane & 15)) * AP_LD + (lane >> 4) * 4) * 4);
    const uint32_t pBase = smem_u32(Ps) + pRowOff;

    auto load_kv = [&](int kt) {
        const int b = kt & 1;
        const uint32_t kb = kvb + (uint32_t)(b * KVBUF) * 4;
        const uint32_t vb = kb + (uint32_t)(KCH * AK_LD) * 4;
        const int kr0 = kt * KCH;
#pragma unroll
        for (int t = 0; t < 4; t++) {            // K: 32 rows x 32 words
            int fid = tid + 256 * t;
            int r = fid >> 5, c4 = (fid & 31) * 4;
            const uint32_t* s = qkv + ((size_t)(kr0 + r) * BATCH + bb) * QKV_N + hoff + HDIM + c4;
            cp16(kb + (uint32_t)(r * AK_LD + c4) * 4, s);
        }
#pragma unroll
        for (int t = 0; t < 4; t++) {            // V^T: 128 rows x 32 words
            int fid = tid + 256 * t;
            int r = fid >> 3, c4 = (fid & 7) * 4;
            cp16(vb + (uint32_t)(r * VT_LD + c4) * 4, vtp + (size_t)r * S_LEN + kr0 + c4);
        }
        asm volatile("cp.async.commit_group;" ::: "memory");
    };

    // prologue: Q tile + KV chunk 0
    {
        uint32_t qsb = smem_u32(Qs);
#pragma unroll
        for (int t = 0; t < 16; t++) {
            int fid = tid + 256 * t;
            int r = fid >> 5, c4 = (fid & 31) * 4;
            const uint32_t* s = qkv + ((size_t)(q0 + r) * BATCH + bb) * QKV_N + hoff + c4;
            cp16(qsb + (uint32_t)(r * AQ_LD + c4) * 4, s);
        }
    }
    load_kv(0);
    asm volatile("cp.async.wait_group 0;" ::: "memory");
    __syncthreads();

    // hoist Q fragments (loop-invariant)
    uint32_t qf[16][4];
    {
        const uint32_t qBase = smem_u32(Qs) + qRowOff;
#pragma unroll
        for (int kk = 0; kk < 16; kk++) ldsm4(qf[kk], qBase + kk * 32);
    }

    const int nkt = 4 * qt + 4;
    if (nkt > 1) load_kv(1);

    float o[16][4];
#pragma unroll
    for (int j = 0; j < 16; j++)
#pragma unroll
        for (int q = 0; q < 4; q++) o[j][q] = 0.f;
    float m0r = -1e30f, m1r = -1e30f, l0r = 0.f, l1r = 0.f;
    const float scale = 0.08838834764831845f;    // 1/sqrt(128)

    for (int kt = 0; kt < nkt; kt++) {
        if (kt > 0) {
            asm volatile("cp.async.wait_group 0;" ::: "memory");
            __syncthreads();
            if (kt + 1 < nkt) load_kv(kt + 1);
        }
        const int b = kt & 1;
        const uint32_t kBase = kvb + (uint32_t)(b * KVBUF) * 4 + kRowOff;
        const uint32_t vBase = kvb + (uint32_t)(b * KVBUF + KCH * AK_LD) * 4 + vRowOff;
        const int kr0 = kt * KCH;
        const int rowg = q0 + warp * 16 + g;
        const bool active = (kr0 <= q0 + warp * 16 + 15);

        if (active) {
            float s[4][4];
#pragma unroll
            for (int j = 0; j < 4; j++)
#pragma unroll
                for (int q = 0; q < 4; q++) s[j][q] = 0.f;
#pragma unroll
            for (int kk = 0; kk < 16; kk++) {
                uint32_t bv0[4], bv1[4];
                ldsm4(bv0, kBase + kk * 32);                              // j tiles 0,1
                ldsm4(bv1, kBase + (uint32_t)(16 * AK_LD) * 4 + kk * 32); // j tiles 2,3
                mma8(s[0], qf[kk], bv0[0], bv0[1]);
                mma8(s[1], qf[kk], bv0[2], bv0[3]);
                mma8(s[2], qf[kk], bv1[0], bv1[1]);
                mma8(s[3], qf[kk], bv1[2], bv1[3]);
            }
#pragma unroll
            for (int j = 0; j < 4; j++) {
                int cb = kr0 + j * 8 + 2 * tg;
                s[j][0] = (cb     > rowg)     ? -10000.f : s[j][0] * scale;
                s[j][1] = (cb + 1 > rowg)     ? -10000.f : s[j][1] * scale;
                s[j][2] = (cb     > rowg + 8) ? -10000.f : s[j][2] * scale;
                s[j][3] = (cb + 1 > rowg + 8) ? -10000.f : s[j][3] * scale;
            }
            {
                float ml = -1e30f;
#pragma unroll
                for (int j = 0; j < 4; j++) ml = fmaxf(ml, fmaxf(s[j][0], s[j][1]));
                ml = fmaxf(ml, __shfl_xor_sync(0xffffffffu, ml, 1));
                ml = fmaxf(ml, __shfl_xor_sync(0xffffffffu, ml, 2));
                float mn = fmaxf(m0r, ml);
                float corr = __expf(m0r - mn);
                float ps = 0.f;
#pragma unroll
                for (int j = 0; j < 4; j++) {
                    s[j][0] = __expf(s[j][0] - mn);
                    s[j][1] = __expf(s[j][1] - mn);
                    ps += s[j][0] + s[j][1];
                }
                ps += __shfl_xor_sync(0xffffffffu, ps, 1);
                ps += __shfl_xor_sync(0xffffffffu, ps, 2);
                l0r = l0r * corr + ps; m0r = mn;
#pragma unroll
                for (int j = 0; j < 16; j++) { o[j][0] *= corr; o[j][1] *= corr; }
            }
            {
                float ml = -1e30f;
#pragma unroll
                for (int j = 0; j < 4; j++) ml = fmaxf(ml, fmaxf(s[j][2], s[j][3]));
                ml = fmaxf(ml, __shfl_xor_sync(0xffffffffu, ml, 1));
                ml = fmaxf(ml, __shfl_xor_sync(0xffffffffu, ml, 2));
                float mn = fmaxf(m1r, ml);
                float corr = __expf(m1r - mn);
                float ps = 0.f;
#pragma unroll
                for (int j = 0; j < 4; j++) {
                    s[j][2] = __expf(s[j][2] - mn);
                    s[j][3] = __expf(s[j][3] - mn);
                    ps += s[j][2] + s[j][3];
                }
                ps += __shfl_xor_sync(0xffffffffu, ps, 1);
                ps += __shfl_xor_sync(0xffffffffu, ps, 2);
                l1r = l1r * corr + ps; m1r = mn;
#pragma unroll
                for (int j = 0; j < 16; j++) { o[j][2] *= corr; o[j][3] *= corr; }
            }
#pragma unroll
            for (int j = 0; j < 4; j++) {
                uint32_t* p0 = Ps + (warp * 16 + g) * AP_LD + j * 8 + 2 * tg;
                p0[0] = f2tf(s[j][0]); p0[1] = f2tf(s[j][1]);
                uint32_t* p1 = p0 + 8 * AP_LD;
                p1[0] = f2tf(s[j][2]); p1[1] = f2tf(s[j][3]);
            }
        }
        __syncwarp();
        if (active) {
            // O += P @ V  via ldmatrix on V^T (n-major, same pattern as K)
#pragma unroll
            for (int kk = 0; kk < 4; kk++) {
                uint32_t a[4];
                ldsm4(a, pBase + kk * 32);
#pragma unroll
                for (int jp = 0; jp < 8; jp++) {
                    uint32_t v[4];
                    ldsm4(v, vBase + (uint32_t)(jp * 16 * VT_LD) * 4 + kk * 32);
                    mma8(o[2 * jp],     a, v[0], v[1]);
                    mma8(o[2 * jp + 1], a, v[2], v[3]);
                }
            }
        }
    }

    const float i0 = 1.f / l0r, i1 = 1.f / l1r;
    const int r0g = q0 + warp * 16 + g;
#pragma unroll
    for (int j = 0; j < 16; j++) {
        int col = head * HDIM + j * 8 + 2 * tg;
        uint2 v0 = { f2tf(o[j][0] * i0), f2tf(o[j][1] * i0) };
        uint2 v1 = { f2tf(o[j][2] * i1), f2tf(o[j][3] * i1) };
        *(uint2*)(ctx + ((size_t)r0g * BATCH + bb) * HID + col) = v0;
        *(uint2*)(ctx + ((size_t)(r0g + 8) * BATCH + bb) * HID + col) = v1;
    }
}

// ---------------------------------------------------------------------------
extern "C" void kernel_launch(void* const* d_in, const int* in_sizes, int n_in,
                              void* d_out, int out_size)
{
    const float* hs      = (const float*)d_in[0];
    const float* w_qkv   = (const float*)d_in[2];
    const float* b_qkv   = (const float*)d_in[3];
    const float* w_dense = (const float*)d_in[4];
    const float* b_dense = (const float*)d_in[5];
    float* out = (float*)d_out;

    uint32_t *hs_t, *wqkv_t, *wd_t, *ctx_t, *qkv_buf, *vt_buf;
    cudaGetSymbolAddress((void**)&hs_t, g_hs_t);
    cudaGetSymbolAddress((void**)&wqkv_t, g_wqkv_t);
    cudaGetSymbolAddress((void**)&wd_t, g_wd_t);
    cudaGetSymbolAddress((void**)&qkv_buf, g_qkv);
    cudaGetSymbolAddress((void**)&vt_buf, g_vt);
    cudaGetSymbolAddress((void**)&ctx_t, g_ctx_t);

    cudaFuncSetAttribute(gemm_tf32, cudaFuncAttributeMaxDynamicSharedMemorySize, GEMM_SMEM_BYTES);
    cudaFuncSetAttribute(attn_tf32, cudaFuncAttributeMaxDynamicSharedMemorySize, ATT_BYTES);

    // 0) pre-round GEMM operands to tf32 (rna)
    {
        int n4;
        n4 = ROWS * HID / 4;
        cvt_tf32_kernel<<<(n4 + 255) / 256, 256>>>((const float4*)hs, (uint4*)hs_t, n4);
        n4 = QKV_N * HID / 4;
        cvt_tf32_kernel<<<(n4 + 255) / 256, 256>>>((const float4*)w_qkv, (uint4*)wqkv_t, n4);
        n4 = HID * HID / 4;
        cvt_tf32_kernel<<<(n4 + 255) / 256, 256>>>((const float4*)w_dense, (uint4*)wd_t, n4);
    }

    // 1) QKV projection: qkv(tf32 bits) = hs @ w_qkv^T + b_qkv
    gemm_tf32<<<dim3(QKV_N / GBN, ROWS / GBM), GTHREADS, GEMM_SMEM_BYTES>>>(
        hs_t, wqkv_t, b_qkv, qkv_buf, ROWS, QKV_N, HID, 1, 1);

    // 1b) transpose V -> vt[b][h][hd][S]
    transpose_v<<<dim3(S_LEN / 32, HDIM / 32, BATCH * NHEAD), 256>>>(qkv_buf, vt_buf);

    // 2) causal flash attention -> ctx (tf32 bits)
    attn_tf32<<<dim3(S_LEN / 128, NHEAD, BATCH), 256, ATT_BYTES>>>(qkv_buf, vt_buf, ctx_t);

    // 3) dense projection: out(fp32) = ctx @ w_dense^T (skip_bias_add)
    gemm_tf32<<<dim3(HID / GBN, ROWS / GBM), GTHREADS, GEMM_SMEM_BYTES>>>(
        ctx_t, wd_t, nullptr, (uint32_t*)out, ROWS, HID, HID, 0, 0);

    // 4) b_dense returned separately -> tail of d_out
    if (out_size >= (int)((size_t)ROWS * HID + HID)) {
        cudaMemcpyAsync(out + (size_t)ROWS * HID, b_dense,
                        HID * sizeof(float), cudaMemcpyDeviceToDevice);
    }
}

// round 13
// speedup vs baseline: 1.2532x; 1.0189x over previous
#include <cuda_runtime.h>
#include <math.h>
#include <stdint.h>

#define S_LEN 2048
#define BATCH 2
#define HID 2048
#define NHEAD 16
#define HDIM 128
#define QKV_N 6144
#define ROWS 4096

// ---------------- scratch (device globals; allocation forbidden) -----------
__device__ uint32_t g_hs_t[(size_t)ROWS * HID];      // tf32 bits of hidden_states
__device__ uint32_t g_wqkv_t[(size_t)QKV_N * HID];   // tf32 bits of w_qkv
__device__ uint32_t g_wd_t[(size_t)HID * HID];       // tf32 bits of w_dense
__device__ uint32_t g_qkv[(size_t)ROWS * QKV_N];     // tf32 bits of qkv
__device__ uint32_t g_vt[(size_t)BATCH * NHEAD * HDIM * S_LEN];  // V transposed
__device__ uint32_t g_ctx_t[(size_t)ROWS * HID];     // tf32 bits of ctx

// ---------------- helpers --------------------------------------------------
__device__ __forceinline__ uint32_t f2tf(float x) {
    uint32_t r; asm("cvt.rna.tf32.f32 %0, %1;" : "=r"(r) : "f"(x)); return r;
}
__device__ __forceinline__ void mma8(float* c, const uint32_t* a, uint32_t b0, uint32_t b1) {
    asm volatile("mma.sync.aligned.m16n8k8.row.col.f32.tf32.tf32.f32 "
        "{%0,%1,%2,%3},{%4,%5,%6,%7},{%8,%9},{%0,%1,%2,%3};"
        : "+f"(c[0]), "+f"(c[1]), "+f"(c[2]), "+f"(c[3])
        : "r"(a[0]), "r"(a[1]), "r"(a[2]), "r"(a[3]), "r"(b0), "r"(b1));
}
__device__ __forceinline__ void ldsm4(uint32_t* r, uint32_t addr) {
    asm volatile("ldmatrix.sync.aligned.m8n8.x4.shared.b16 {%0,%1,%2,%3}, [%4];"
        : "=r"(r[0]), "=r"(r[1]), "=r"(r[2]), "=r"(r[3]) : "r"(addr));
}
__device__ __forceinline__ void cp16(uint32_t saddr, const void* gptr) {
    asm volatile("cp.async.cg.shared.global [%0], [%1], 16;" :: "r"(saddr), "l"(gptr));
}
__device__ __forceinline__ uint32_t smem_u32(const void* p) {
    uint32_t a;
    asm("{ .reg .u64 t; cvta.to.shared.u64 t, %1; cvt.u32.u64 %0, t; }" : "=r"(a) : "l"(p));
    return a;
}

#define MBAR_INIT(addr, cnt) \
    asm volatile("mbarrier.init.shared.b64 [%0], %1;" :: "r"(addr), "r"(cnt) : "memory")
#define MBAR_ARRIVE(addr) \
    asm volatile("mbarrier.arrive.shared.b64 _, [%0];" :: "r"(addr) : "memory")
#define MBAR_ARRIVE_CPASYNC(addr) \
    asm volatile("cp.async.mbarrier.arrive.noinc.shared.b64 [%0];" :: "r"(addr) : "memory")
#define MBAR_WAIT(addr, par) do {                                               \
    uint32_t _done;                                                             \
    asm volatile("{ .reg .pred p; mbarrier.try_wait.parity.acquire.cta.shared::cta.b64 p, [%1], %2; selp.b32 %0,1,0,p; }" \
        : "=r"(_done) : "r"(addr), "r"(par) : "memory");                        \
    while (!_done) {                                                            \
        asm volatile("{ .reg .pred p; mbarrier.try_wait.parity.acquire.cta.shared::cta.b64 p, [%1], %2, 0x989680; selp.b32 %0,1,0,p; }" \
            : "=r"(_done) : "r"(addr), "r"(par) : "memory");                    \
    }                                                                           \
} while (0)

// ---------------- fp32 -> tf32 conversion kernel ---------------------------
__global__ void cvt_tf32_kernel(const float4* __restrict__ in, uint4* __restrict__ out, int n4) {
    int i = blockIdx.x * blockDim.x + threadIdx.x;
    if (i < n4) {
        float4 v = in[i];
        uint4 o;
        o.x = f2tf(v.x); o.y = f2tf(v.y); o.z = f2tf(v.z); o.w = f2tf(v.w);
        out[i] = o;
    }
}

// ---------------- V transpose: qkv V columns -> vt[b][h][hd][S] -------------
__global__ __launch_bounds__(256, 4)
void transpose_v(const uint32_t* __restrict__ qkv, uint32_t* __restrict__ vt)
{
    __shared__ uint32_t tile[32][33];
    const int st = blockIdx.x;
    const int ht = blockIdx.y;
    const int bh = blockIdx.z;
    const int head = bh & 15, bb = bh >> 4;
    const int tx = threadIdx.x & 31, ty = threadIdx.x >> 5;

#pragma unroll
    for (int rr = 0; rr < 4; rr++) {
        int s = st * 32 + ty + rr * 8;
        int hd = ht * 32 + tx;
        tile[ty + rr * 8][tx] =
            qkv[((size_t)s * BATCH + bb) * QKV_N + head * 384 + 2 * HDIM + hd];
    }
    __syncthreads();
#pragma unroll
    for (int rr = 0; rr < 4; rr++) {
        int hd = ht * 32 + ty + rr * 8;
        int s = st * 32 + tx;
        vt[((size_t)(bb * NHEAD + head) * HDIM + hd) * S_LEN + s] = tile[tx][ty + rr * 8];
    }
}

// ---------------- tf32 GEMM: unchanged from R11 ------------------------------
#define GBM 128
#define GBN 128
#define GBK 32
#define SLD 36
#define TSZ (128 * SLD)
#define GEMM_SMEM_BYTES (3 * 2 * TSZ * 4)       // 110592
#define GTHREADS 256

__global__ __launch_bounds__(GTHREADS, 2)
void gemm_tf32(const uint32_t* __restrict__ A, const uint32_t* __restrict__ B,
               const float* __restrict__ bias, uint32_t* __restrict__ C,
               int M, int N, int K, int add_bias, int out_tf32)
{
    extern __shared__ uint32_t sm[];
    __shared__ uint64_t bars[6];

    const int tid = threadIdx.x;
    const int lane = tid & 31, warp = tid >> 5;
    const int g = lane >> 2, tg = lane & 3;
    const int wm = warp >> 2, wn = warp & 3;
    const int m0 = blockIdx.y * GBM, n0 = blockIdx.x * GBN;
    const uint32_t smb = smem_u32(sm);
    const uint32_t barb = smem_u32(bars);
#define FULLB(s)  (barb + 8u * (uint32_t)(s))
#define EMPTYB(s) (barb + 24u + 8u * (uint32_t)(s))

    if (tid == 0) {
#pragma unroll
        for (int s = 0; s < 3; s++) {
            MBAR_INIT(FULLB(s), GTHREADS);
            MBAR_INIT(EMPTYB(s), GTHREADS);
        }
    }
    __syncthreads();

    const uint32_t aRowOff = (uint32_t)(((wm * 64 + (lane & 15)) * SLD + (lane >> 4) * 4) * 4);
    const uint32_t bRowOff = (uint32_t)(((wn * 32 + ((lane >> 4) & 1) * 8 + (lane & 7)) * SLD
                                         + ((lane >> 3) & 1) * 4) * 4);

    float c[4][4][4];
#pragma unroll
    for (int i = 0; i < 4; i++)
#pragma unroll
        for (int j = 0; j < 4; j++)
#pragma unroll
            for (int q = 0; q < 4; q++) c[i][j][q] = 0.f;

    auto load_stage = [&](int it) {
        const int buf = it % 3;
        uint32_t ab = smb + (uint32_t)(buf * 2 * TSZ) * 4;
        uint32_t bb = ab + (uint32_t)TSZ * 4;
        const int k0 = it * GBK;
#pragma unroll
        for (int t = 0; t < 4; t++) {
            int fid = tid + GTHREADS * t;
            int r = fid >> 3, c4 = (fid & 7) * 4;
            cp16(ab + (uint32_t)(r * SLD + c4) * 4, A + (size_t)(m0 + r) * K + k0 + c4);
            cp16(bb + (uint32_t)(r * SLD + c4) * 4, B + (size_t)(n0 + r) * K + k0 + c4);
        }
        MBAR_ARRIVE_CPASYNC(FULLB(buf));
    };

    const int NI = K / GBK;
    load_stage(0);
    load_stage(1);

    for (int it = 0; it < NI; it++) {
        const int nx = it + 2;
        if (nx < NI) {
            const int qn = nx % 3, rn = nx / 3;
            if (rn >= 1) MBAR_WAIT(EMPTYB(qn), (uint32_t)((rn - 1) & 1));
            load_stage(nx);
        }
        const int q = it % 3;
        MBAR_WAIT(FULLB(q), (uint32_t)((it / 3) & 1));

        const uint32_t aBase = smb + (uint32_t)(q * 2 * TSZ) * 4 + aRowOff;
        const uint32_t bBase = smb + (uint32_t)(q * 2 * TSZ + TSZ) * 4 + bRowOff;
#pragma unroll
        for (int kk = 0; kk < 4; kk++) {
            uint32_t a[4][4], bv[2][4];
#pragma unroll
            for (int i = 0; i < 4; i++)
                ldsm4(a[i], aBase + (uint32_t)(i * 16 * SLD) * 4 + kk * 32);
#pragma unroll
            for (int jp = 0; jp < 2; jp++)
                ldsm4(bv[jp], bBase + (uint32_t)(jp * 16 * SLD) * 4 + kk * 32);
#pragma unroll
            for (int jp = 0; jp < 2; jp++)
#pragma unroll
                for (int i = 0; i < 4; i++) {
                    mma8(c[i][2 * jp],     a[i], bv[jp][0], bv[jp][1]);
                    mma8(c[i][2 * jp + 1], a[i], bv[jp][2], bv[jp][3]);
                }
        }
        MBAR_ARRIVE(EMPTYB(q));
    }

#pragma unroll
    for (int i = 0; i < 4; i++) {
        int row = m0 + wm * 64 + i * 16 + g;
#pragma unroll
        for (int j = 0; j < 4; j++) {
            int col = n0 + wn * 32 + j * 8 + 2 * tg;
            float b0 = add_bias ? bias[col] : 0.f;
            float b1 = add_bias ? bias[col + 1] : 0.f;
            float v00 = c[i][j][0] + b0, v01 = c[i][j][1] + b1;
            float v10 = c[i][j][2] + b0, v11 = c[i][j][3] + b1;
            uint2 r0, r1;
            if (out_tf32) {
                r0.x = f2tf(v00); r0.y = f2tf(v01);
                r1.x = f2tf(v10); r1.y = f2tf(v11);
            } else {
                r0.x = __float_as_uint(v00); r0.y = __float_as_uint(v01);
                r1.x = __float_as_uint(v10); r1.y = __float_as_uint(v11);
            }
            *(uint2*)(C + (size_t)row * N + col) = r0;
            *(uint2*)(C + (size_t)(row + 8) * N + col) = r1;
        }
    }
#undef FULLB
#undef EMPTYB
}

// ---------------- tf32 flash attention, KCH=64 -------------------------------
// Q tile 128 (fragments in regs; Q smem staging aliases KV buffer 1).
// K chunk [64][AK_LD] + V^T chunk [128][VT_LD=68] double-buffered.
#define AQ_LD 132
#define AK_LD 132
#define VT_LD 68
#define AP_LD 68
#define KCH 64
#define KVBUF (KCH * AK_LD + HDIM * VT_LD)      // 8448 + 8704 = 17152 words
#define ATT_WORDS (2 * KVBUF + 128 * AP_LD)     // 34304 + 8704 = 43008
#define ATT_BYTES (ATT_WORDS * 4)               // 172032

__global__ __launch_bounds__(256, 1)
void attn_tf32(const uint32_t* __restrict__ qkv, const uint32_t* __restrict__ vt,
               uint32_t* __restrict__ ctx)
{
    extern __shared__ uint32_t sm[];
    uint32_t* KV = sm;                           // 2 x KVBUF
    uint32_t* Ps = KV + 2 * KVBUF;
    const uint32_t kvb = smem_u32(KV);

    const int tid = threadIdx.x, lane = tid & 31, warp = tid >> 5;
    const int g = lane >> 2, tg = lane & 3;
    const int qt = gridDim.x - 1 - blockIdx.x;   // heavy tiles first
    const int head = blockIdx.y, bb = blockIdx.z;
    const int q0 = qt * 128;
    const size_t hoff = (size_t)head * (3 * HDIM);
    const uint32_t* vtp = vt + (size_t)(bb * NHEAD + head) * HDIM * S_LEN;

    // ldmatrix row offsets
    const uint32_t qRowOff = (uint32_t)(((warp * 16 + (lane & 15)) * AQ_LD + (lane >> 4) * 4) * 4);
    const uint32_t kRowOff = (uint32_t)(((((lane >> 4) & 1) * 8 + (lane & 7)) * AK_LD
                                         + ((lane >> 3) & 1) * 4) * 4);
    const uint32_t vRowOff = (uint32_t)(((((lane >> 4) & 1) * 8 + (lane & 7)) * VT_LD
                                         + ((lane >> 3) & 1) * 4) * 4);
    const uint32_t pRowOff = (uint32_t)(((warp * 16 + (lane & 15)) * AP_LD + (lane >> 4) * 4) * 4);
    const uint32_t pBase = smem_u32(Ps) + pRowOff;

    auto load_kv = [&](int kt) {
        const int b = kt & 1;
        const uint32_t kb = kvb + (uint32_t)(b * KVBUF) * 4;
        const uint32_t vb = kb + (uint32_t)(KCH * AK_LD) * 4;
        const int kr0 = kt * KCH;
#pragma unroll
        for (int t = 0; t < 8; t++) {            // K: 64 rows x 32 16B-chunks
            int fid = tid + 256 * t;
            int r = fid >> 5, c4 = (fid & 31) * 4;
            const uint32_t* s = qkv + ((size_t)(kr0 + r) * BATCH + bb) * QKV_N + hoff + HDIM + c4;
            cp16(kb + (uint32_t)(r * AK_LD + c4) * 4, s);
        }
#pragma unroll
        for (int t = 0; t < 8; t++) {            // V^T: 128 rows x 16 chunks
            int fid = tid + 256 * t;
            int r = fid >> 4, c4 = (fid & 15) * 4;
            cp16(vb + (uint32_t)(r * VT_LD + c4) * 4, vtp + (size_t)r * S_LEN + kr0 + c4);
        }
        asm volatile("cp.async.commit_group;" ::: "memory");
    };

    // prologue: stage Q into KV buffer 1 (dead after fragment hoist)
    {
        const uint32_t qstage = kvb + (uint32_t)KVBUF * 4;
#pragma unroll
        for (int t = 0; t < 16; t++) {
            int fid = tid + 256 * t;
            int r = fid >> 5, c4 = (fid & 31) * 4;
            const uint32_t* s = qkv + ((size_t)(q0 + r) * BATCH + bb) * QKV_N + hoff + c4;
            cp16(qstage + (uint32_t)(r * AQ_LD + c4) * 4, s);
        }
        asm volatile("cp.async.commit_group;" ::: "memory");
        asm volatile("cp.async.wait_group 0;" ::: "memory");
        __syncthreads();
    }

    uint32_t qf[16][4];
    {
        const uint32_t qBase = kvb + (uint32_t)KVBUF * 4 + qRowOff;
#pragma unroll
        for (int kk = 0; kk < 16; kk++) ldsm4(qf[kk], qBase + kk * 32);
    }
    __syncthreads();                             // all hoists done before buf1 overwrite

    const int nkt = 2 * qt + 2;
    load_kv(0);
    asm volatile("cp.async.wait_group 0;" ::: "memory");
    __syncthreads();
    if (nkt > 1) load_kv(1);

    float o[16][4];
#pragma unroll
    for (int j = 0; j < 16; j++)
#pragma unroll
        for (int q = 0; q < 4; q++) o[j][q] = 0.f;
    float m0r = -1e30f, m1r = -1e30f, l0r = 0.f, l1r = 0.f;
    const float scale = 0.08838834764831845f;    // 1/sqrt(128)

    for (int kt = 0; kt < nkt; kt++) {
        if (kt > 0) {
            asm volatile("cp.async.wait_group 0;" ::: "memory");
            __syncthreads();
            if (kt + 1 < nkt) load_kv(kt + 1);
        }
        const int b = kt & 1;
        const uint32_t kBase = kvb + (uint32_t)(b * KVBUF) * 4 + kRowOff;
        const uint32_t vBase = kvb + (uint32_t)(b * KVBUF + KCH * AK_LD) * 4 + vRowOff;
        const int kr0 = kt * KCH;
        const int rowg = q0 + warp * 16 + g;
        const bool active = (kr0 <= q0 + warp * 16 + 15);

        if (active) {
            float s[8][4];
#pragma unroll
            for (int j = 0; j < 8; j++)
#pragma unroll
                for (int q = 0; q < 4; q++) s[j][q] = 0.f;
#pragma unroll
            for (int kk = 0; kk < 16; kk++) {
                uint32_t bv[4][4];
#pragma unroll
                for (int jt = 0; jt < 4; jt++)
                    ldsm4(bv[jt], kBase + (uint32_t)(jt * 16 * AK_LD) * 4 + kk * 32);
#pragma unroll
                for (int jt = 0; jt < 4; jt++) {
                    mma8(s[2 * jt],     qf[kk], bv[jt][0], bv[jt][1]);
                    mma8(s[2 * jt + 1], qf[kk], bv[jt][2], bv[jt][3]);
                }
            }
#pragma unroll
            for (int j = 0; j < 8; j++) {
                int cb = kr0 + j * 8 + 2 * tg;
                s[j][0] = (cb     > rowg)     ? -10000.f : s[j][0] * scale;
                s[j][1] = (cb + 1 > rowg)     ? -10000.f : s[j][1] * scale;
                s[j][2] = (cb     > rowg + 8) ? -10000.f : s[j][2] * scale;
                s[j][3] = (cb + 1 > rowg + 8) ? -10000.f : s[j][3] * scale;
            }
            {
                float ml = -1e30f;
#pragma unroll
                for (int j = 0; j < 8; j++) ml = fmaxf(ml, fmaxf(s[j][0], s[j][1]));
                ml = fmaxf(ml, __shfl_xor_sync(0xffffffffu, ml, 1));
                ml = fmaxf(ml, __shfl_xor_sync(0xffffffffu, ml, 2));
                float mn = fmaxf(m0r, ml);
                float corr = __expf(m0r - mn);
                float ps = 0.f;
#pragma unroll
                for (int j = 0; j < 8; j++) {
                    s[j][0] = __expf(s[j][0] - mn);
                    s[j][1] = __expf(s[j][1] - mn);
                    ps += s[j][0] + s[j][1];
                }
                ps += __shfl_xor_sync(0xffffffffu, ps, 1);
                ps += __shfl_xor_sync(0xffffffffu, ps, 2);
                l0r = l0r * corr + ps; m0r = mn;
#pragma unroll
                for (int j = 0; j < 16; j++) { o[j][0] *= corr; o[j][1] *= corr; }
            }
            {
                float ml = -1e30f;
#pragma unroll
                for (int j = 0; j < 8; j++) ml = fmaxf(ml, fmaxf(s[j][2], s[j][3]));
                ml = fmaxf(ml, __shfl_xor_sync(0xffffffffu, ml, 1));
                ml = fmaxf(ml, __shfl_xor_sync(0xffffffffu, ml, 2));
                float mn = fmaxf(m1r, ml);
                float corr = __expf(m1r - mn);
                float ps = 0.f;
#pragma unroll
                for (int j = 0; j < 8; j++) {
                    s[j][2] = __expf(s[j][2] - mn);
                    s[j][3] = __expf(s[j][3] - mn);
                    ps += s[j][2] + s[j][3];
                }
                ps += __shfl_xor_sync(0xffffffffu, ps, 1);
                ps += __shfl_xor_sync(0xffffffffu, ps, 2);
                l1r = l1r * corr + ps; m1r = mn;
#pragma unroll
                for (int j = 0; j < 16; j++) { o[j][2] *= corr; o[j][3] *= corr; }
            }
#pragma unroll
            for (int j = 0; j < 8; j++) {
                uint32_t* p0 = Ps + (warp * 16 + g) * AP_LD + j * 8 + 2 * tg;
                p0[0] = f2tf(s[j][0]); p0[1] = f2tf(s[j][1]);
                uint32_t* p1 = p0 + 8 * AP_LD;
                p1[0] = f2tf(s[j][2]); p1[1] = f2tf(s[j][3]);
            }
        }
        __syncwarp();
        if (active) {
            // O += P @ V via ldmatrix on V^T (k = 64)
#pragma unroll
            for (int kk = 0; kk < 8; kk++) {
                uint32_t a[4];
                ldsm4(a, pBase + kk * 32);
#pragma unroll
                for (int jp = 0; jp < 8; jp++) {
                    uint32_t v[4];
                    ldsm4(v, vBase + (uint32_t)(jp * 16 * VT_LD) * 4 + kk * 32);
                    mma8(o[2 * jp],     a, v[0], v[1]);
                    mma8(o[2 * jp + 1], a, v[2], v[3]);
                }
            }
        }
    }

    const float i0 = 1.f / l0r, i1 = 1.f / l1r;
    const int r0g = q0 + warp * 16 + g;
#pragma unroll
    for (int j = 0; j < 16; j++) {
        int col = head * HDIM + j * 8 + 2 * tg;
        uint2 v0 = { f2tf(o[j][0] * i0), f2tf(o[j][1] * i0) };
        uint2 v1 = { f2tf(o[j][2] * i1), f2tf(o[j][3] * i1) };
        *(uint2*)(ctx + ((size_t)r0g * BATCH + bb) * HID + col) = v0;
        *(uint2*)(ctx + ((size_t)(r0g + 8) * BATCH + bb) * HID + col) = v1;
    }
}

// ---------------------------------------------------------------------------
extern "C" void kernel_launch(void* const* d_in, const int* in_sizes, int n_in,
                              void* d_out, int out_size)
{
    const float* hs      = (const float*)d_in[0];
    const float* w_qkv   = (const float*)d_in[2];
    const float* b_qkv   = (const float*)d_in[3];
    const float* w_dense = (const float*)d_in[4];
    const float* b_dense = (const float*)d_in[5];
    float* out = (float*)d_out;

    uint32_t *hs_t, *wqkv_t, *wd_t, *ctx_t, *qkv_buf, *vt_buf;
    cudaGetSymbolAddress((void**)&hs_t, g_hs_t);
    cudaGetSymbolAddress((void**)&wqkv_t, g_wqkv_t);
    cudaGetSymbolAddress((void**)&wd_t, g_wd_t);
    cudaGetSymbolAddress((void**)&qkv_buf, g_qkv);
    cudaGetSymbolAddress((void**)&vt_buf, g_vt);
    cudaGetSymbolAddress((void**)&ctx_t, g_ctx_t);

    cudaFuncSetAttribute(gemm_tf32, cudaFuncAttributeMaxDynamicSharedMemorySize, GEMM_SMEM_BYTES);
    cudaFuncSetAttribute(attn_tf32, cudaFuncAttributeMaxDynamicSharedMemorySize, ATT_BYTES);

    // 0) pre-round GEMM operands to tf32 (rna)
    {
        int n4;
        n4 = ROWS * HID / 4;
        cvt_tf32_kernel<<<(n4 + 255) / 256, 256>>>((const float4*)hs, (uint4*)hs_t, n4);
        n4 = QKV_N * HID / 4;
        cvt_tf32_kernel<<<(n4 + 255) / 256, 256>>>((const float4*)w_qkv, (uint4*)wqkv_t, n4);
        n4 = HID * HID / 4;
        cvt_tf32_kernel<<<(n4 + 255) / 256, 256>>>((const float4*)w_dense, (uint4*)wd_t, n4);
    }

    // 1) QKV projection: qkv(tf32 bits) = hs @ w_qkv^T + b_qkv
    gemm_tf32<<<dim3(QKV_N / GBN, ROWS / GBM), GTHREADS, GEMM_SMEM_BYTES>>>(
        hs_t, wqkv_t, b_qkv, qkv_buf, ROWS, QKV_N, HID, 1, 1);

    // 1b) transpose V -> vt[b][h][hd][S]
    transpose_v<<<dim3(S_LEN / 32, HDIM / 32, BATCH * NHEAD), 256>>>(qkv_buf, vt_buf);

    // 2) causal flash attention -> ctx (tf32 bits)
    attn_tf32<<<dim3(S_LEN / 128, NHEAD, BATCH), 256, ATT_BYTES>>>(qkv_buf, vt_buf, ctx_t);

    // 3) dense projection: out(fp32) = ctx @ w_dense^T (skip_bias_add)
    gemm_tf32<<<dim3(HID / GBN, ROWS / GBM), GTHREADS, GEMM_SMEM_BYTES>>>(
        ctx_t, wd_t, nullptr, (uint32_t*)out, ROWS, HID, HID, 0, 0);

    // 4) b_dense returned separately -> tail of d_out
    if (out_size >= (int)((size_t)ROWS * HID + HID)) {
        cudaMemcpyAsync(out + (size_t)ROWS * HID, b_dense,
                        HID * sizeof(float), cudaMemcpyDeviceToDevice);
    }
}

// round 14
// speedup vs baseline: 1.2813x; 1.0224x over previous
#include <cuda_runtime.h>
#include <math.h>
#include <stdint.h>

#define S_LEN 2048
#define BATCH 2
#define HID 2048
#define NHEAD 16
#define HDIM 128
#define QKV_N 6144
#define ROWS 4096

// ---------------- scratch (device globals; allocation forbidden) -----------
__device__ uint32_t g_hs_t[(size_t)ROWS * HID];      // tf32 bits of hidden_states
__device__ uint32_t g_wqkv_t[(size_t)QKV_N * HID];   // tf32 bits of w_qkv
__device__ uint32_t g_wd_t[(size_t)HID * HID];       // tf32 bits of w_dense
__device__ uint32_t g_qkv[(size_t)ROWS * QKV_N];     // tf32 bits of qkv
__device__ uint32_t g_vt[(size_t)BATCH * NHEAD * HDIM * S_LEN];  // V transposed
__device__ uint32_t g_ctx_t[(size_t)ROWS * HID];     // tf32 bits of ctx

// ---------------- helpers --------------------------------------------------
__device__ __forceinline__ uint32_t f2tf(float x) {
    uint32_t r; asm("cvt.rna.tf32.f32 %0, %1;" : "=r"(r) : "f"(x)); return r;
}
__device__ __forceinline__ float ex2(float x) {
    float y; asm("ex2.approx.f32 %0, %1;" : "=f"(y) : "f"(x)); return y;
}
__device__ __forceinline__ void mma8(float* c, const uint32_t* a, uint32_t b0, uint32_t b1) {
    asm volatile("mma.sync.aligned.m16n8k8.row.col.f32.tf32.tf32.f32 "
        "{%0,%1,%2,%3},{%4,%5,%6,%7},{%8,%9},{%0,%1,%2,%3};"
        : "+f"(c[0]), "+f"(c[1]), "+f"(c[2]), "+f"(c[3])
        : "r"(a[0]), "r"(a[1]), "r"(a[2]), "r"(a[3]), "r"(b0), "r"(b1));
}
__device__ __forceinline__ void ldsm4(uint32_t* r, uint32_t addr) {
    asm volatile("ldmatrix.sync.aligned.m8n8.x4.shared.b16 {%0,%1,%2,%3}, [%4];"
        : "=r"(r[0]), "=r"(r[1]), "=r"(r[2]), "=r"(r[3]) : "r"(addr));
}
__device__ __forceinline__ void cp16(uint32_t saddr, const void* gptr) {
    asm volatile("cp.async.cg.shared.global [%0], [%1], 16;" :: "r"(saddr), "l"(gptr));
}
__device__ __forceinline__ uint32_t smem_u32(const void* p) {
    uint32_t a;
    asm("{ .reg .u64 t; cvta.to.shared.u64 t, %1; cvt.u32.u64 %0, t; }" : "=r"(a) : "l"(p));
    return a;
}

#define MBAR_INIT(addr, cnt) \
    asm volatile("mbarrier.init.shared.b64 [%0], %1;" :: "r"(addr), "r"(cnt) : "memory")
#define MBAR_ARRIVE(addr) \
    asm volatile("mbarrier.arrive.shared.b64 _, [%0];" :: "r"(addr) : "memory")
#define MBAR_ARRIVE_CPASYNC(addr) \
    asm volatile("cp.async.mbarrier.arrive.noinc.shared.b64 [%0];" :: "r"(addr) : "memory")
#define MBAR_WAIT(addr, par) do {                                               \
    uint32_t _done;                                                             \
    asm volatile("{ .reg .pred p; mbarrier.try_wait.parity.acquire.cta.shared::cta.b64 p, [%1], %2; selp.b32 %0,1,0,p; }" \
        : "=r"(_done) : "r"(addr), "r"(par) : "memory");                        \
    while (!_done) {                                                            \
        asm volatile("{ .reg .pred p; mbarrier.try_wait.parity.acquire.cta.shared::cta.b64 p, [%1], %2, 0x989680; selp.b32 %0,1,0,p; }" \
            : "=r"(_done) : "r"(addr), "r"(par) : "memory");                    \
    }                                                                           \
} while (0)

// ---------------- fp32 -> tf32 conversion kernel ---------------------------
__global__ void cvt_tf32_kernel(const float4* __restrict__ in, uint4* __restrict__ out, int n4) {
    int i = blockIdx.x * blockDim.x + threadIdx.x;
    if (i < n4) {
        float4 v = in[i];
        uint4 o;
        o.x = f2tf(v.x); o.y = f2tf(v.y); o.z = f2tf(v.z); o.w = f2tf(v.w);
        out[i] = o;
    }
}

// ---------------- V transpose: qkv V columns -> vt[b][h][hd][S] -------------
__global__ __launch_bounds__(256, 4)
void transpose_v(const uint32_t* __restrict__ qkv, uint32_t* __restrict__ vt)
{
    __shared__ uint32_t tile[32][33];
    const int st = blockIdx.x;
    const int ht = blockIdx.y;
    const int bh = blockIdx.z;
    const int head = bh & 15, bb = bh >> 4;
    const int tx = threadIdx.x & 31, ty = threadIdx.x >> 5;

#pragma unroll
    for (int rr = 0; rr < 4; rr++) {
        int s = st * 32 + ty + rr * 8;
        int hd = ht * 32 + tx;
        tile[ty + rr * 8][tx] =
            qkv[((size_t)s * BATCH + bb) * QKV_N + head * 384 + 2 * HDIM + hd];
    }
    __syncthreads();
#pragma unroll
    for (int rr = 0; rr < 4; rr++) {
        int hd = ht * 32 + ty + rr * 8;
        int s = st * 32 + tx;
        vt[((size_t)(bb * NHEAD + head) * HDIM + hd) * S_LEN + s] = tile[tx][ty + rr * 8];
    }
}

// ---------------- tf32 GEMM: unchanged from R11/R12 -------------------------
#define GBM 128
#define GBN 128
#define GBK 32
#define SLD 36
#define TSZ (128 * SLD)
#define GEMM_SMEM_BYTES (3 * 2 * TSZ * 4)       // 110592
#define GTHREADS 256

__global__ __launch_bounds__(GTHREADS, 2)
void gemm_tf32(const uint32_t* __restrict__ A, const uint32_t* __restrict__ B,
               const float* __restrict__ bias, uint32_t* __restrict__ C,
               int M, int N, int K, int add_bias, int out_tf32)
{
    extern __shared__ uint32_t sm[];
    __shared__ uint64_t bars[6];

    const int tid = threadIdx.x;
    const int lane = tid & 31, warp = tid >> 5;
    const int g = lane >> 2, tg = lane & 3;
    const int wm = warp >> 2, wn = warp & 3;
    const int m0 = blockIdx.y * GBM, n0 = blockIdx.x * GBN;
    const uint32_t smb = smem_u32(sm);
    const uint32_t barb = smem_u32(bars);
#define FULLB(s)  (barb + 8u * (uint32_t)(s))
#define EMPTYB(s) (barb + 24u + 8u * (uint32_t)(s))

    if (tid == 0) {
#pragma unroll
        for (int s = 0; s < 3; s++) {
            MBAR_INIT(FULLB(s), GTHREADS);
            MBAR_INIT(EMPTYB(s), GTHREADS);
        }
    }
    __syncthreads();

    const uint32_t aRowOff = (uint32_t)(((wm * 64 + (lane & 15)) * SLD + (lane >> 4) * 4) * 4);
    const uint32_t bRowOff = (uint32_t)(((wn * 32 + ((lane >> 4) & 1) * 8 + (lane & 7)) * SLD
                                         + ((lane >> 3) & 1) * 4) * 4);

    float c[4][4][4];
#pragma unroll
    for (int i = 0; i < 4; i++)
#pragma unroll
        for (int j = 0; j < 4; j++)
#pragma unroll
            for (int q = 0; q < 4; q++) c[i][j][q] = 0.f;

    auto load_stage = [&](int it) {
        const int buf = it % 3;
        uint32_t ab = smb + (uint32_t)(buf * 2 * TSZ) * 4;
        uint32_t bb = ab + (uint32_t)TSZ * 4;
        const int k0 = it * GBK;
#pragma unroll
        for (int t = 0; t < 4; t++) {
            int fid = tid + GTHREADS * t;
            int r = fid >> 3, c4 = (fid & 7) * 4;
            cp16(ab + (uint32_t)(r * SLD + c4) * 4, A + (size_t)(m0 + r) * K + k0 + c4);
            cp16(bb + (uint32_t)(r * SLD + c4) * 4, B + (size_t)(n0 + r) * K + k0 + c4);
        }
        MBAR_ARRIVE_CPASYNC(FULLB(buf));
    };

    const int NI = K / GBK;
    load_stage(0);
    load_stage(1);

    for (int it = 0; it < NI; it++) {
        const int nx = it + 2;
        if (nx < NI) {
            const int qn = nx % 3, rn = nx / 3;
            if (rn >= 1) MBAR_WAIT(EMPTYB(qn), (uint32_t)((rn - 1) & 1));
            load_stage(nx);
        }
        const int q = it % 3;
        MBAR_WAIT(FULLB(q), (uint32_t)((it / 3) & 1));

        const uint32_t aBase = smb + (uint32_t)(q * 2 * TSZ) * 4 + aRowOff;
        const uint32_t bBase = smb + (uint32_t)(q * 2 * TSZ + TSZ) * 4 + bRowOff;
#pragma unroll
        for (int kk = 0; kk < 4; kk++) {
            uint32_t a[4][4], bv[2][4];
#pragma unroll
            for (int i = 0; i < 4; i++)
                ldsm4(a[i], aBase + (uint32_t)(i * 16 * SLD) * 4 + kk * 32);
#pragma unroll
            for (int jp = 0; jp < 2; jp++)
                ldsm4(bv[jp], bBase + (uint32_t)(jp * 16 * SLD) * 4 + kk * 32);
#pragma unroll
            for (int jp = 0; jp < 2; jp++)
#pragma unroll
                for (int i = 0; i < 4; i++) {
                    mma8(c[i][2 * jp],     a[i], bv[jp][0], bv[jp][1]);
                    mma8(c[i][2 * jp + 1], a[i], bv[jp][2], bv[jp][3]);
                }
        }
        MBAR_ARRIVE(EMPTYB(q));
    }

#pragma unroll
    for (int i = 0; i < 4; i++) {
        int row = m0 + wm * 64 + i * 16 + g;
#pragma unroll
        for (int j = 0; j < 4; j++) {
            int col = n0 + wn * 32 + j * 8 + 2 * tg;
            float b0 = add_bias ? bias[col] : 0.f;
            float b1 = add_bias ? bias[col + 1] : 0.f;
            float v00 = c[i][j][0] + b0, v01 = c[i][j][1] + b1;
            float v10 = c[i][j][2] + b0, v11 = c[i][j][3] + b1;
            uint2 r0, r1;
            if (out_tf32) {
                r0.x = f2tf(v00); r0.y = f2tf(v01);
                r1.x = f2tf(v10); r1.y = f2tf(v11);
            } else {
                r0.x = __float_as_uint(v00); r0.y = __float_as_uint(v01);
                r1.x = __float_as_uint(v10); r1.y = __float_as_uint(v11);
            }
            *(uint2*)(C + (size_t)row * N + col) = r0;
            *(uint2*)(C + (size_t)(row + 8) * N + col) = r1;
        }
    }
#undef FULLB
#undef EMPTYB
}

// ---------------- tf32 flash attention, KCH=64, mbarrier ring ----------------
// Q tile 128 (fragments in regs; Q smem staging aliases KV buffer 1).
// 2-stage full/empty mbarrier ring replaces wait_group+__syncthreads.
// Softmax runs in exp2 domain (scale folded with log2e).
#define AQ_LD 132
#define AK_LD 132
#define VT_LD 68
#define AP_LD 68
#define KCH 64
#define KVBUF (KCH * AK_LD + HDIM * VT_LD)      // 8448 + 8704 = 17152 words
#define ATT_WORDS (2 * KVBUF + 128 * AP_LD)     // 43008
#define ATT_BYTES (ATT_WORDS * 4)               // 172032

__global__ __launch_bounds__(256, 1)
void attn_tf32(const uint32_t* __restrict__ qkv, const uint32_t* __restrict__ vt,
               uint32_t* __restrict__ ctx)
{
    extern __shared__ uint32_t sm[];
    uint32_t* KV = sm;                           // 2 x KVBUF
    uint32_t* Ps = KV + 2 * KVBUF;
    const uint32_t kvb = smem_u32(KV);
    __shared__ uint64_t abars[4];                // full[0..1], empty[0..1]
    const uint32_t abarb = smem_u32(abars);
#define AFULL(s)  (abarb + 8u * (uint32_t)(s))
#define AEMPTY(s) (abarb + 16u + 8u * (uint32_t)(s))

    const int tid = threadIdx.x, lane = tid & 31, warp = tid >> 5;
    const int g = lane >> 2, tg = lane & 3;
    const int qt = gridDim.x - 1 - blockIdx.x;   // heavy tiles first
    const int head = blockIdx.y, bb = blockIdx.z;
    const int q0 = qt * 128;
    const size_t hoff = (size_t)head * (3 * HDIM);
    const uint32_t* vtp = vt + (size_t)(bb * NHEAD + head) * HDIM * S_LEN;

    if (tid == 0) {
#pragma unroll
        for (int s = 0; s < 2; s++) {
            MBAR_INIT(AFULL(s), 256);
            MBAR_INIT(AEMPTY(s), 256);
        }
    }
    __syncthreads();

    // ldmatrix row offsets
    const uint32_t qRowOff = (uint32_t)(((warp * 16 + (lane & 15)) * AQ_LD + (lane >> 4) * 4) * 4);
    const uint32_t kRowOff = (uint32_t)(((((lane >> 4) & 1) * 8 + (lane & 7)) * AK_LD
                                         + ((lane >> 3) & 1) * 4) * 4);
    const uint32_t vRowOff = (uint32_t)(((((lane >> 4) & 1) * 8 + (lane & 7)) * VT_LD
                                         + ((lane >> 3) & 1) * 4) * 4);
    const uint32_t pRowOff = (uint32_t)(((warp * 16 + (lane & 15)) * AP_LD + (lane >> 4) * 4) * 4);
    const uint32_t pBase = smem_u32(Ps) + pRowOff;

    auto load_kv = [&](int kt) {
        const int b = kt & 1;
        const uint32_t kb = kvb + (uint32_t)(b * KVBUF) * 4;
        const uint32_t vb = kb + (uint32_t)(KCH * AK_LD) * 4;
        const int kr0 = kt * KCH;
#pragma unroll
        for (int t = 0; t < 8; t++) {            // K: 64 rows x 32 16B-chunks
            int fid = tid + 256 * t;
            int r = fid >> 5, c4 = (fid & 31) * 4;
            const uint32_t* s = qkv + ((size_t)(kr0 + r) * BATCH + bb) * QKV_N + hoff + HDIM + c4;
            cp16(kb + (uint32_t)(r * AK_LD + c4) * 4, s);
        }
#pragma unroll
        for (int t = 0; t < 8; t++) {            // V^T: 128 rows x 16 chunks
            int fid = tid + 256 * t;
            int r = fid >> 4, c4 = (fid & 15) * 4;
            cp16(vb + (uint32_t)(r * VT_LD + c4) * 4, vtp + (size_t)r * S_LEN + kr0 + c4);
        }
        MBAR_ARRIVE_CPASYNC(AFULL(b));
    };

    // prologue: stage Q into KV buffer 1 (dead after fragment hoist)
    {
        const uint32_t qstage = kvb + (uint32_t)KVBUF * 4;
#pragma unroll
        for (int t = 0; t < 16; t++) {
            int fid = tid + 256 * t;
            int r = fid >> 5, c4 = (fid & 31) * 4;
            const uint32_t* s = qkv + ((size_t)(q0 + r) * BATCH + bb) * QKV_N + hoff + c4;
            cp16(qstage + (uint32_t)(r * AQ_LD + c4) * 4, s);
        }
        asm volatile("cp.async.commit_group;" ::: "memory");
        asm volatile("cp.async.wait_group 0;" ::: "memory");
        __syncthreads();
    }

    uint32_t qf[16][4];
    {
        const uint32_t qBase = kvb + (uint32_t)KVBUF * 4 + qRowOff;
#pragma unroll
        for (int kk = 0; kk < 16; kk++) ldsm4(qf[kk], qBase + kk * 32);
    }
    __syncthreads();                             // all hoists done before buf1 overwrite

    const int nkt = 2 * qt + 2;
    load_kv(0);

    float o[16][4];
#pragma unroll
    for (int j = 0; j < 16; j++)
#pragma unroll
        for (int q = 0; q < 4; q++) o[j][q] = 0.f;
    float m0r = -1e30f, m1r = -1e30f, l0r = 0.f, l1r = 0.f;
    // scale folded with log2(e): softmax in exp2 domain
    const float scale2 = 0.08838834764831845f * 1.4426950408889634f;
    const float MASK2 = -14426.95f;              // -10000 * log2(e)

    for (int kt = 0; kt < nkt; kt++) {
        if (kt + 1 < nkt) {
            if (kt >= 1) MBAR_WAIT(AEMPTY((kt + 1) & 1), (uint32_t)((((kt + 1) >> 1) - 1) & 1));
            load_kv(kt + 1);
        }
        MBAR_WAIT(AFULL(kt & 1), (uint32_t)((kt >> 1) & 1));

        const int b = kt & 1;
        const uint32_t kBase = kvb + (uint32_t)(b * KVBUF) * 4 + kRowOff;
        const uint32_t vBase = kvb + (uint32_t)(b * KVBUF + KCH * AK_LD) * 4 + vRowOff;
        const int kr0 = kt * KCH;
        const int rowg = q0 + warp * 16 + g;
        const bool active = (kr0 <= q0 + warp * 16 + 15);

        if (active) {
            float s[8][4];
#pragma unroll
            for (int j = 0; j < 8; j++)
#pragma unroll
                for (int q = 0; q < 4; q++) s[j][q] = 0.f;
#pragma unroll
            for (int kk = 0; kk < 16; kk++) {
                uint32_t bv[4][4];
#pragma unroll
                for (int jt = 0; jt < 4; jt++)
                    ldsm4(bv[jt], kBase + (uint32_t)(jt * 16 * AK_LD) * 4 + kk * 32);
#pragma unroll
                for (int jt = 0; jt < 4; jt++) {
                    mma8(s[2 * jt],     qf[kk], bv[jt][0], bv[jt][1]);
                    mma8(s[2 * jt + 1], qf[kk], bv[jt][2], bv[jt][3]);
                }
            }
#pragma unroll
            for (int j = 0; j < 8; j++) {
                int cb = kr0 + j * 8 + 2 * tg;
                s[j][0] = (cb     > rowg)     ? MASK2 : s[j][0] * scale2;
                s[j][1] = (cb + 1 > rowg)     ? MASK2 : s[j][1] * scale2;
                s[j][2] = (cb     > rowg + 8) ? MASK2 : s[j][2] * scale2;
                s[j][3] = (cb + 1 > rowg + 8) ? MASK2 : s[j][3] * scale2;
            }
            {
                float ml = -1e30f;
#pragma unroll
                for (int j = 0; j < 8; j++) ml = fmaxf(ml, fmaxf(s[j][0], s[j][1]));
                ml = fmaxf(ml, __shfl_xor_sync(0xffffffffu, ml, 1));
                ml = fmaxf(ml, __shfl_xor_sync(0xffffffffu, ml, 2));
                float mn = fmaxf(m0r, ml);
                float corr = ex2(m0r - mn);
                float ps = 0.f;
#pragma unroll
                for (int j = 0; j < 8; j++) {
                    s[j][0] = ex2(s[j][0] - mn);
                    s[j][1] = ex2(s[j][1] - mn);
                    ps += s[j][0] + s[j][1];
                }
                ps += __shfl_xor_sync(0xffffffffu, ps, 1);
                ps += __shfl_xor_sync(0xffffffffu, ps, 2);
                l0r = l0r * corr + ps; m0r = mn;
#pragma unroll
                for (int j = 0; j < 16; j++) { o[j][0] *= corr; o[j][1] *= corr; }
            }
            {
                float ml = -1e30f;
#pragma unroll
                for (int j = 0; j < 8; j++) ml = fmaxf(ml, fmaxf(s[j][2], s[j][3]));
                ml = fmaxf(ml, __shfl_xor_sync(0xffffffffu, ml, 1));
                ml = fmaxf(ml, __shfl_xor_sync(0xffffffffu, ml, 2));
                float mn = fmaxf(m1r, ml);
                float corr = ex2(m1r - mn);
                float ps = 0.f;
#pragma unroll
                for (int j = 0; j < 8; j++) {
                    s[j][2] = ex2(s[j][2] - mn);
                    s[j][3] = ex2(s[j][3] - mn);
                    ps += s[j][2] + s[j][3];
                }
                ps += __shfl_xor_sync(0xffffffffu, ps, 1);
                ps += __shfl_xor_sync(0xffffffffu, ps, 2);
                l1r = l1r * corr + ps; m1r = mn;
#pragma unroll
                for (int j = 0; j < 16; j++) { o[j][2] *= corr; o[j][3] *= corr; }
            }
#pragma unroll
            for (int j = 0; j < 8; j++) {
                uint32_t* p0 = Ps + (warp * 16 + g) * AP_LD + j * 8 + 2 * tg;
                uint2 w0 = { f2tf(s[j][0]), f2tf(s[j][1]) };
                uint2 w1 = { f2tf(s[j][2]), f2tf(s[j][3]) };
                *(uint2*)p0 = w0;
                *(uint2*)(p0 + 8 * AP_LD) = w1;
            }
        }
        __syncwarp();
        if (active) {
            // O += P @ V via ldmatrix on V^T (k = 64)
#pragma unroll
            for (int kk = 0; kk < 8; kk++) {
                uint32_t a[4];
                ldsm4(a, pBase + kk * 32);
#pragma unroll
                for (int jp = 0; jp < 8; jp++) {
                    uint32_t v[4];
                    ldsm4(v, vBase + (uint32_t)(jp * 16 * VT_LD) * 4 + kk * 32);
                    mma8(o[2 * jp],     a, v[0], v[1]);
                    mma8(o[2 * jp + 1], a, v[2], v[3]);
                }
            }
        }
        MBAR_ARRIVE(AEMPTY(kt & 1));
    }

    const float i0 = 1.f / l0r, i1 = 1.f / l1r;
    const int r0g = q0 + warp * 16 + g;
#pragma unroll
    for (int j = 0; j < 16; j++) {
        int col = head * HDIM + j * 8 + 2 * tg;
        uint2 v0 = { f2tf(o[j][0] * i0), f2tf(o[j][1] * i0) };
        uint2 v1 = { f2tf(o[j][2] * i1), f2tf(o[j][3] * i1) };
        *(uint2*)(ctx + ((size_t)r0g * BATCH + bb) * HID + col) = v0;
        *(uint2*)(ctx + ((size_t)(r0g + 8) * BATCH + bb) * HID + col) = v1;
    }
#undef AFULL
#undef AEMPTY
}

// ---------------------------------------------------------------------------
extern "C" void kernel_launch(void* const* d_in, const int* in_sizes, int n_in,
                              void* d_out, int out_size)
{
    const float* hs      = (const float*)d_in[0];
    const float* w_qkv   = (const float*)d_in[2];
    const float* b_qkv   = (const float*)d_in[3];
    const float* w_dense = (const float*)d_in[4];
    const float* b_dense = (const float*)d_in[5];
    float* out = (float*)d_out;

    uint32_t *hs_t, *wqkv_t, *wd_t, *ctx_t, *qkv_buf, *vt_buf;
    cudaGetSymbolAddress((void**)&hs_t, g_hs_t);
    cudaGetSymbolAddress((void**)&wqkv_t, g_wqkv_t);
    cudaGetSymbolAddress((void**)&wd_t, g_wd_t);
    cudaGetSymbolAddress((void**)&qkv_buf, g_qkv);
    cudaGetSymbolAddress((void**)&vt_buf, g_vt);
    cudaGetSymbolAddress((void**)&ctx_t, g_ctx_t);

    cudaFuncSetAttribute(gemm_tf32, cudaFuncAttributeMaxDynamicSharedMemorySize, GEMM_SMEM_BYTES);
    cudaFuncSetAttribute(attn_tf32, cudaFuncAttributeMaxDynamicSharedMemorySize, ATT_BYTES);

    // 0) pre-round GEMM operands to tf32 (rna)
    {
        int n4;
        n4 = ROWS * HID / 4;
        cvt_tf32_kernel<<<(n4 + 255) / 256, 256>>>((const float4*)hs, (uint4*)hs_t, n4);
        n4 = QKV_N * HID / 4;
        cvt_tf32_kernel<<<(n4 + 255) / 256, 256>>>((const float4*)w_qkv, (uint4*)wqkv_t, n4);
        n4 = HID * HID / 4;
        cvt_tf32_kernel<<<(n4 + 255) / 256, 256>>>((const float4*)w_dense, (uint4*)wd_t, n4);
    }

    // 1) QKV projection: qkv(tf32 bits) = hs @ w_qkv^T + b_qkv
    gemm_tf32<<<dim3(QKV_N / GBN, ROWS / GBM), GTHREADS, GEMM_SMEM_BYTES>>>(
        hs_t, wqkv_t, b_qkv, qkv_buf, ROWS, QKV_N, HID, 1, 1);

    // 1b) transpose V -> vt[b][h][hd][S]
    transpose_v<<<dim3(S_LEN / 32, HDIM / 32, BATCH * NHEAD), 256>>>(qkv_buf, vt_buf);

    // 2) causal flash attention -> ctx (tf32 bits)
    attn_tf32<<<dim3(S_LEN / 128, NHEAD, BATCH), 256, ATT_BYTES>>>(qkv_buf, vt_buf, ctx_t);

    // 3) dense projection: out(fp32) = ctx @ w_dense^T (skip_bias_add)
    gemm_tf32<<<dim3(HID / GBN, ROWS / GBM), GTHREADS, GEMM_SMEM_BYTES>>>(
        ctx_t, wd_t, nullptr, (uint32_t*)out, ROWS, HID, HID, 0, 0);

    // 4) b_dense returned separately -> tail of d_out
    if (out_size >= (int)((size_t)ROWS * HID + HID)) {
        cudaMemcpyAsync(out + (size_t)ROWS * HID, b_dense,
                        HID * sizeof(float), cudaMemcpyDeviceToDevice);
    }
}